// round 5
// baseline (speedup 1.0000x reference)
#include <cuda_runtime.h>
#include <cuda_bf16.h>
#include <math.h>
#include <stdint.h>

// ---------------- problem constants ----------------
#define N_SAMP 2048
#define D_DIM  512
#define C_CLS  10000
#define CK     30000
#define CK_PAD 30720
#define ARC_S  30.0f
#define COS_M  0.9210609940028851f   // cos(0.4)
#define SIN_M  0.3894183423086505f   // sin(0.4)
#define TRIP_M 0.3f

#define ABN      96                  // arc tile N (32 classes)
#define NTILES_G 313                 // ceil(30000/96)

// ---------------- scratch ----------------
__device__ __align__(128) float         g_e[N_SAMP * D_DIM];
__device__ __align__(128) __nv_bfloat16 g_e_hi[N_SAMP * D_DIM];
__device__ __align__(128) __nv_bfloat16 g_e_lo[N_SAMP * D_DIM];
__device__ __align__(128) __nv_bfloat16 g_wt_hi[CK_PAD * D_DIM];  // zero-padded rows >= 30000
__device__ __align__(128) __nv_bfloat16 g_wt_lo[CK_PAD * D_DIM];
__device__ float  g_invw[CK];
__device__ float  g_arc_m[N_SAMP * NTILES_G];
__device__ float  g_arc_s[N_SAMP * NTILES_G];
__device__ float  g_lab[N_SAMP];
__device__ int    g_dap[N_SAMP];
__device__ int    g_dan[N_SAMP];
__device__ double g_arc_sum, g_tl_sum, g_center_sum;
__device__ int    g_nnz;

// ---------------- PTX helpers (sm_80-era, plain-target safe) ----------------
__device__ __forceinline__ uint32_t smem_u32(const void* p) {
    uint32_t a;
    asm("{ .reg .u64 t; cvta.to.shared.u64 t, %1; cvt.u32.u64 %0, t; }" : "=r"(a) : "l"(p));
    return a;
}
__device__ __forceinline__ void cp16(uint32_t dst, const void* src) {
    asm volatile("cp.async.cg.shared.global [%0], [%1], 16;" :: "r"(dst), "l"(src) : "memory");
}
#define CP_COMMIT() asm volatile("cp.async.commit_group;" ::: "memory")
#define CP_WAIT2()  asm volatile("cp.async.wait_group 2;" ::: "memory")

__device__ __forceinline__ void ldsm4(uint32_t* r, uint32_t addr) {
    asm volatile("ldmatrix.sync.aligned.m8n8.x4.shared.b16 {%0,%1,%2,%3}, [%4];"
        : "=r"(r[0]), "=r"(r[1]), "=r"(r[2]), "=r"(r[3]) : "r"(addr));
}
__device__ __forceinline__ void mma16816(float* d, const uint32_t* a, uint32_t b0, uint32_t b1) {
    asm volatile("mma.sync.aligned.m16n8k16.row.col.f32.bf16.bf16.f32 "
        "{%0,%1,%2,%3}, {%4,%5,%6,%7}, {%8,%9}, {%0,%1,%2,%3};"
        : "+f"(d[0]), "+f"(d[1]), "+f"(d[2]), "+f"(d[3])
        : "r"(a[0]), "r"(a[1]), "r"(a[2]), "r"(a[3]), "r"(b0), "r"(b1));
}

__device__ __forceinline__ void lse_merge(float& M, float& S, float m2, float s2) {
    if (m2 > M) { S = S * expf(M - m2) + s2; M = m2; }
    else        { S += s2 * expf(m2 - M); }
}

// ---------------- prep kernels ----------------
__global__ void k_init() {
    int i = blockIdx.x * blockDim.x + threadIdx.x;
    if (i < N_SAMP) { g_dap[i] = __float_as_int(-1.0f); g_dan[i] = __float_as_int(3.0f); }
    if (i == 0) { g_arc_sum = 0.0; g_tl_sum = 0.0; g_center_sum = 0.0; g_nnz = 0; }
}

__global__ void k_norm_emb(const float* __restrict__ emb) {
    int row = blockIdx.x, tid = threadIdx.x;
    const float* src = emb + row * D_DIM;
    float s = 0.f;
    for (int d = tid; d < D_DIM; d += 256) { float v = src[d]; s += v * v; }
    __shared__ float red[256];
    red[tid] = s; __syncthreads();
    for (int st = 128; st > 0; st >>= 1) { if (tid < st) red[tid] += red[tid + st]; __syncthreads(); }
    float inv = 1.f / fmaxf(sqrtf(red[0]), 1e-12f);
    for (int d = tid; d < D_DIM; d += 256) {
        float v = src[d] * inv;
        g_e[row * D_DIM + d] = v;
        __nv_bfloat16 h = __float2bfloat16(v);
        g_e_hi[row * D_DIM + d] = h;
        g_e_lo[row * D_DIM + d] = __float2bfloat16(v - __bfloat162float(h));
    }
}

__global__ void k_wnorm(const float* __restrict__ W) {
    int j = blockIdx.x * blockDim.x + threadIdx.x;
    if (j >= CK) return;
    float s = 0.f;
    #pragma unroll 8
    for (int k = 0; k < D_DIM; k++) { float v = W[k * CK + j]; s += v * v; }
    g_invw[j] = 1.f / fmaxf(sqrtf(s), 1e-12f);
}

__global__ void k_wtrans(const float* __restrict__ W) {
    __shared__ float tile[32][33];
    int j0 = blockIdx.x * 32, k0 = blockIdx.y * 32;
    int tx = threadIdx.x, ty = threadIdx.y;
    #pragma unroll
    for (int i = 0; i < 32; i += 8) {
        int k = k0 + ty + i, j = j0 + tx;
        tile[ty + i][tx] = (j < CK) ? W[k * CK + j] : 0.f;
    }
    __syncthreads();
    #pragma unroll
    for (int i = 0; i < 32; i += 8) {
        int j = j0 + ty + i, k = k0 + tx;
        if (j < CK) {
            float v = tile[tx][ty + i] * g_invw[j];
            __nv_bfloat16 h = __float2bfloat16(v);
            g_wt_hi[j * D_DIM + k] = h;
            g_wt_lo[j * D_DIM + k] = __float2bfloat16(v - __bfloat162float(h));
        }
    }
}

// ============================================================================
// arc GEMM: 128x96 tile, 3-pass bf16 mma.sync, 4-stage cp.async pipeline,
// ONE __syncthreads per K-chunk. SMEM rows 80B (conflict-free ldmatrix).
// Stage: A_hi 10240 | A_lo 10240 | B_hi 7680 | B_lo 7680 = 35840
// ============================================================================
#define A_OFF_AL 10240
#define A_OFF_BH 20480
#define A_OFF_BL 28160
#define A_STG    35840
#define A_NSTG   4
#define A_SMEM   (A_NSTG * A_STG)   // 143360; epilogue reuses 51200

__device__ __forceinline__ void load_arc_stage(uint32_t st, int kc, int rowA, int colB, int tid) {
    int gk = kc * 32;
    #pragma unroll
    for (int i = 0; i < 2; i++) {
        int idx = tid + i * 256;
        int row = idx >> 2, c = idx & 3;
        uint32_t so = row * 80 + c * 16;
        cp16(st + so,            &g_e_hi[(rowA + row) * D_DIM + gk + c * 8]);
        cp16(st + A_OFF_AL + so, &g_e_lo[(rowA + row) * D_DIM + gk + c * 8]);
    }
    {
        int row = tid >> 2, c = tid & 3;
        uint32_t so = row * 80 + c * 16;
        cp16(st + A_OFF_BH + so, &g_wt_hi[(colB + row) * D_DIM + gk + c * 8]);
        cp16(st + A_OFF_BL + so, &g_wt_lo[(colB + row) * D_DIM + gk + c * 8]);
    }
    if (tid < 128) {
        int idx = tid + 256;
        int row = idx >> 2, c = idx & 3;
        uint32_t so = row * 80 + c * 16;
        cp16(st + A_OFF_BH + so, &g_wt_hi[(colB + row) * D_DIM + gk + c * 8]);
        cp16(st + A_OFF_BL + so, &g_wt_lo[(colB + row) * D_DIM + gk + c * 8]);
    }
}

__global__ void __launch_bounds__(256, 1) k_gemm_arc(const int* __restrict__ labels) {
    extern __shared__ char smem[];
    uint32_t sb = smem_u32(smem);
    int tid = threadIdx.x, wid = tid >> 5, lane = tid & 31;
    int warpM = wid & 3, warpN = wid >> 2;          // 4M x 2N
    int rowA = blockIdx.x * 128;
    int tileN = blockIdx.y;
    int colB = tileN * ABN;

    float acc[2][6][4];
    #pragma unroll
    for (int a = 0; a < 2; a++)
        #pragma unroll
        for (int b = 0; b < 6; b++)
            #pragma unroll
            for (int c = 0; c < 4; c++) acc[a][b][c] = 0.f;

    int lrow = lane & 15, lhalf = lane >> 4;
    uint32_t aoff[2], boff[3];
    #pragma unroll
    for (int mt = 0; mt < 2; mt++) aoff[mt] = (warpM * 32 + mt * 16 + lrow) * 80 + lhalf * 16;
    #pragma unroll
    for (int bt = 0; bt < 3; bt++) boff[bt] = (warpN * 48 + bt * 16 + lrow) * 80 + lhalf * 16;

    // prologue: stages 0..2 in flight (3 groups pending)
    #pragma unroll
    for (int s = 0; s < A_NSTG - 1; s++) {
        load_arc_stage(sb + s * A_STG, s, rowA, colB, tid);
        CP_COMMIT();
    }

    for (int kc = 0; kc < 16; kc++) {
        CP_WAIT2();          // retire group for stage kc (3 pending -> 2)
        __syncthreads();     // all threads' stage-kc data visible; stage kc%4 free after prev compute
        if (kc + A_NSTG - 1 < 16)
            load_arc_stage(sb + ((kc + A_NSTG - 1) & 3) * A_STG, kc + A_NSTG - 1, rowA, colB, tid);
        CP_COMMIT();         // always commit (possibly empty) to keep pending invariant
        uint32_t st = sb + (kc & 3) * A_STG;
        #pragma unroll
        for (int ks = 0; ks < 2; ks++) {
            uint32_t ah[2][4], al[2][4], bh[3][4], bl[3][4];
            #pragma unroll
            for (int mt = 0; mt < 2; mt++) {
                ldsm4(ah[mt], st + aoff[mt] + ks * 32);
                ldsm4(al[mt], st + A_OFF_AL + aoff[mt] + ks * 32);
            }
            #pragma unroll
            for (int bt = 0; bt < 3; bt++) {
                ldsm4(bh[bt], st + A_OFF_BH + boff[bt] + ks * 32);
                ldsm4(bl[bt], st + A_OFF_BL + boff[bt] + ks * 32);
            }
            // pass-outer ordering: consecutive mmas hit different accumulators
            #pragma unroll
            for (int mt = 0; mt < 2; mt++)
                #pragma unroll
                for (int nt = 0; nt < 6; nt++) {
                    int bt = nt >> 1, sel = nt & 1;
                    mma16816(acc[mt][nt], ah[mt], bh[bt][sel], bh[bt][sel | 2]);
                }
            #pragma unroll
            for (int mt = 0; mt < 2; mt++)
                #pragma unroll
                for (int nt = 0; nt < 6; nt++) {
                    int bt = nt >> 1, sel = nt & 1;
                    mma16816(acc[mt][nt], ah[mt], bl[bt][sel], bl[bt][sel | 2]);
                }
            #pragma unroll
            for (int mt = 0; mt < 2; mt++)
                #pragma unroll
                for (int nt = 0; nt < 6; nt++) {
                    int bt = nt >> 1, sel = nt & 1;
                    mma16816(acc[mt][nt], al[mt], bh[bt][sel], bh[bt][sel | 2]);
                }
        }
    }

    // ---- epilogue: accum -> smem (pitch 100 fp32), fused subcenter/margin/lse ----
    __syncthreads();
    float* se = (float*)smem;
    #pragma unroll
    for (int mt = 0; mt < 2; mt++) {
        int r = warpM * 32 + mt * 16 + (lane >> 2);
        #pragma unroll
        for (int nt = 0; nt < 6; nt++) {
            int c = warpN * 48 + nt * 8 + ((lane & 3) << 1);
            se[r * 100 + c]           = acc[mt][nt][0];
            se[r * 100 + c + 1]       = acc[mt][nt][1];
            se[(r + 8) * 100 + c]     = acc[mt][nt][2];
            se[(r + 8) * 100 + c + 1] = acc[mt][nt][3];
        }
    }
    __syncthreads();

    int r = tid >> 1, h = tid & 1;
    int gi = rowA + r;
    int lab = labels[gi];
    int cbase = tileN * 32 + h * 16;
    const float* row = se + r * 100 + h * 48;
    float M = -1e30f, S = 0.f;
    #pragma unroll
    for (int g = 0; g < 16; g++) {
        int c = cbase + g;
        if (c >= C_CLS) break;
        float cm = fmaxf(fmaxf(row[3*g], row[3*g+1]), row[3*g+2]);
        float logit;
        if (c == lab) {
            float cc = fminf(fmaxf(cm, -1.f + 1e-7f), 1.f - 1e-7f);
            float sn = sqrtf(fmaxf(1.f - cc * cc, 0.f));
            logit = ARC_S * (cc * COS_M - sn * SIN_M);
            g_lab[gi] = logit;
        } else {
            logit = ARC_S * cm;
        }
        lse_merge(M, S, logit, 1.f);
    }
    float pM = __shfl_xor_sync(0xffffffffu, M, 1);
    float pS = __shfl_xor_sync(0xffffffffu, S, 1);
    lse_merge(M, S, pM, pS);
    if (h == 0) {
        g_arc_m[gi * NTILES_G + tileN] = M;
        g_arc_s[gi * NTILES_G + tileN] = S;
    }
}

__global__ void k_arc_reduce() {
    int row = blockIdx.x, tid = threadIdx.x;
    float M = -1e30f, S = 0.f;
    for (int t = tid; t < NTILES_G; t += 256)
        lse_merge(M, S, g_arc_m[row * NTILES_G + t], g_arc_s[row * NTILES_G + t]);
    __shared__ float sm[256], ss[256];
    sm[tid] = M; ss[tid] = S;
    __syncthreads();
    for (int st = 128; st > 0; st >>= 1) {
        if (tid < st) {
            float m1 = sm[tid], s1 = ss[tid];
            lse_merge(m1, s1, sm[tid + st], ss[tid + st]);
            sm[tid] = m1; ss[tid] = s1;
        }
        __syncthreads();
    }
    if (tid == 0) {
        float lse = sm[0] + logf(ss[0]);
        atomicAdd(&g_arc_sum, (double)(lse - g_lab[row]));
    }
}

// ============================================================================
// sim GEMM: 128x128 tile, 4-stage pipeline, fused triplet epilogue
// Stage: A_hi 10240 | A_lo 10240 | B_hi 10240 | B_lo 10240 = 40960
// ============================================================================
#define S_OFF_AL 10240
#define S_OFF_BH 20480
#define S_OFF_BL 30720
#define S_STG    40960
#define S_NSTG   4
#define S_SMEM   (S_NSTG * S_STG + 512)

__device__ __forceinline__ void load_sim_stage(uint32_t st, int kc, int rowA, int colB, int tid) {
    int gk = kc * 32;
    #pragma unroll
    for (int i = 0; i < 2; i++) {
        int idx = tid + i * 256;
        int row = idx >> 2, c = idx & 3;
        uint32_t so = row * 80 + c * 16;
        cp16(st + so,            &g_e_hi[(rowA + row) * D_DIM + gk + c * 8]);
        cp16(st + S_OFF_AL + so, &g_e_lo[(rowA + row) * D_DIM + gk + c * 8]);
        cp16(st + S_OFF_BH + so, &g_e_hi[(colB + row) * D_DIM + gk + c * 8]);
        cp16(st + S_OFF_BL + so, &g_e_lo[(colB + row) * D_DIM + gk + c * 8]);
    }
}

__global__ void __launch_bounds__(256, 1) k_gemm_sim(const int* __restrict__ labels) {
    extern __shared__ char smem[];
    uint32_t sb = smem_u32(smem);
    int tid = threadIdx.x, wid = tid >> 5, lane = tid & 31;
    int warpM = wid & 3, warpN = wid >> 2;          // 4M x 2N
    int rowA = blockIdx.x * 128;
    int colB = blockIdx.y * 128;

    int* slab = (int*)(smem + S_NSTG * S_STG);
    if (tid < 128) slab[tid] = labels[colB + tid];

    float acc[2][8][4];
    #pragma unroll
    for (int a = 0; a < 2; a++)
        #pragma unroll
        for (int b = 0; b < 8; b++)
            #pragma unroll
            for (int c = 0; c < 4; c++) acc[a][b][c] = 0.f;

    int lrow = lane & 15, lhalf = lane >> 4;
    uint32_t aoff[2], boff[4];
    #pragma unroll
    for (int mt = 0; mt < 2; mt++) aoff[mt] = (warpM * 32 + mt * 16 + lrow) * 80 + lhalf * 16;
    #pragma unroll
    for (int bt = 0; bt < 4; bt++) boff[bt] = (warpN * 64 + bt * 16 + lrow) * 80 + lhalf * 16;

    #pragma unroll
    for (int s = 0; s < S_NSTG - 1; s++) {
        load_sim_stage(sb + s * S_STG, s, rowA, colB, tid);
        CP_COMMIT();
    }

    for (int kc = 0; kc < 16; kc++) {
        CP_WAIT2();
        __syncthreads();
        if (kc + S_NSTG - 1 < 16)
            load_sim_stage(sb + ((kc + S_NSTG - 1) & 3) * S_STG, kc + S_NSTG - 1, rowA, colB, tid);
        CP_COMMIT();
        uint32_t st = sb + (kc & 3) * S_STG;
        #pragma unroll
        for (int ks = 0; ks < 2; ks++) {
            uint32_t ah[2][4], al[2][4], bh[4][4], bl[4][4];
            #pragma unroll
            for (int mt = 0; mt < 2; mt++) {
                ldsm4(ah[mt], st + aoff[mt] + ks * 32);
                ldsm4(al[mt], st + S_OFF_AL + aoff[mt] + ks * 32);
            }
            #pragma unroll
            for (int bt = 0; bt < 4; bt++) {
                ldsm4(bh[bt], st + S_OFF_BH + boff[bt] + ks * 32);
                ldsm4(bl[bt], st + S_OFF_BL + boff[bt] + ks * 32);
            }
            #pragma unroll
            for (int mt = 0; mt < 2; mt++)
                #pragma unroll
                for (int nt = 0; nt < 8; nt++) {
                    int bt = nt >> 1, sel = nt & 1;
                    mma16816(acc[mt][nt], ah[mt], bh[bt][sel], bh[bt][sel | 2]);
                }
            #pragma unroll
            for (int mt = 0; mt < 2; mt++)
                #pragma unroll
                for (int nt = 0; nt < 8; nt++) {
                    int bt = nt >> 1, sel = nt & 1;
                    mma16816(acc[mt][nt], ah[mt], bl[bt][sel], bl[bt][sel | 2]);
                }
            #pragma unroll
            for (int mt = 0; mt < 2; mt++)
                #pragma unroll
                for (int nt = 0; nt < 8; nt++) {
                    int bt = nt >> 1, sel = nt & 1;
                    mma16816(acc[mt][nt], al[mt], bh[bt][sel], bh[bt][sel | 2]);
                }
        }
    }

    // ---- fused triplet epilogue: per-thread local, quad-shfl reduce, atomics ----
    #pragma unroll
    for (int mt = 0; mt < 2; mt++) {
        #pragma unroll
        for (int ro = 0; ro < 2; ro++) {
            int r = warpM * 32 + mt * 16 + (lane >> 2) + ro * 8;
            int gi = rowA + r;
            int myl = __ldg(&labels[gi]);
            float dap = -1.f, dan = 3.f;
            #pragma unroll
            for (int nt = 0; nt < 8; nt++) {
                #pragma unroll
                for (int j = 0; j < 2; j++) {
                    int cl = warpN * 64 + nt * 8 + ((lane & 3) << 1) + j;
                    int gj = colB + cl;
                    float sim  = acc[mt][nt][ro * 2 + j];
                    float dist = sqrtf(fmaxf(2.f - 2.f * sim, 0.f));
                    if (slab[cl] == myl) { if (gj != gi) dap = fmaxf(dap, dist); }
                    else                 { dan = fminf(dan, dist); }
                }
            }
            #pragma unroll
            for (int off = 1; off < 4; off <<= 1) {
                dap = fmaxf(dap, __shfl_xor_sync(0xffffffffu, dap, off));
                dan = fminf(dan, __shfl_xor_sync(0xffffffffu, dan, off));
            }
            if ((lane & 3) == 0) {
                atomicMax(&g_dap[gi], __float_as_int(dap));
                atomicMin(&g_dan[gi], __float_as_int(dan));
            }
        }
    }
}

__global__ void k_trip_final() {
    int i = blockIdx.x * blockDim.x + threadIdx.x;
    if (i >= N_SAMP) return;
    float dap = __int_as_float(g_dap[i]);
    float dan = __int_as_float(g_dan[i]);
    bool valid = (dap >= 0.f) && (dan < 2.5f);
    float tl = valid ? fmaxf(dap - dan + TRIP_M, 0.f) : 0.f;
    if (tl > 0.f) {
        atomicAdd(&g_tl_sum, (double)tl);
        atomicAdd(&g_nnz, 1);
    }
}

__global__ void k_center(const int* __restrict__ labels, const float* __restrict__ centers) {
    int row = blockIdx.x, tid = threadIdx.x;
    int lab = labels[row];
    const float* c = centers + lab * D_DIM;
    const float* e = g_e + row * D_DIM;
    float s = 0.f;
    for (int d = tid; d < D_DIM; d += 256) { float diff = e[d] - c[d]; s += diff * diff; }
    __shared__ float red[256];
    red[tid] = s; __syncthreads();
    for (int st = 128; st > 0; st >>= 1) { if (tid < st) red[tid] += red[tid + st]; __syncthreads(); }
    if (tid == 0) atomicAdd(&g_center_sum, (double)red[0]);
}

__global__ void k_final(float* __restrict__ out) {
    double arc  = g_arc_sum / (double)N_SAMP;
    int    nnz  = g_nnz > 1 ? g_nnz : 1;
    double trip = g_tl_sum / (double)nnz;
    double cen  = g_center_sum / (double)N_SAMP;
    out[0] = (float)(arc + 0.5 * trip + 0.01 * cen);
}

// ---------------- launch ----------------
extern "C" void kernel_launch(void* const* d_in, const int* in_sizes, int n_in,
                              void* d_out, int out_size) {
    const float* emb     = (const float*)d_in[0];
    const int*   labels  = (const int*)  d_in[1];
    const float* W       = (const float*)d_in[2];
    const float* centers = (const float*)d_in[3];
    float* out = (float*)d_out;

    cudaFuncSetAttribute(k_gemm_arc, cudaFuncAttributeMaxDynamicSharedMemorySize, A_SMEM);
    cudaFuncSetAttribute(k_gemm_sim, cudaFuncAttributeMaxDynamicSharedMemorySize, S_SMEM);

    k_init<<<2, 1024>>>();
    k_norm_emb<<<N_SAMP, 256>>>(emb);
    k_wnorm<<<(CK + 255) / 256, 256>>>(W);
    k_wtrans<<<dim3((CK + 31) / 32, D_DIM / 32), dim3(32, 8)>>>(W);

    k_gemm_arc<<<dim3(16, NTILES_G), 256, A_SMEM>>>(labels);
    k_arc_reduce<<<N_SAMP, 256>>>();

    k_gemm_sim<<<dim3(16, 16), 256, S_SMEM>>>(labels);
    k_trip_final<<<8, 256>>>();

    k_center<<<N_SAMP, 256>>>(labels, centers);
    k_final<<<1, 1>>>(out);
}

// round 7
// speedup vs baseline: 1.5313x; 1.5313x over previous
#include <cuda_runtime.h>
#include <cuda_bf16.h>
#include <math.h>
#include <stdint.h>

// ---------------- problem constants ----------------
#define N_SAMP 2048
#define D_DIM  512
#define C_CLS  10000
#define CK     30000
#define CK_PAD 30720
#define ARC_S  30.0f
#define COS_M  0.9210609940028851f   // cos(0.4)
#define SIN_M  0.3894183423086505f   // sin(0.4)
#define TRIP_M 0.3f

#define ABN      96                  // arc tile N (32 classes)
#define NTILES_G 313                 // ceil(30000/96) -> cols < 30048 (zero-padded)
#define RP       144                 // SMEM row pitch bytes: 32 fp32 + 4 pad (+4 banks/row)

// ---------------- scratch ----------------
__device__ __align__(128) float g_e[N_SAMP * D_DIM];    // exact normalized (center loss)
__device__ __align__(128) float g_et[N_SAMP * D_DIM];   // tf32-rounded normalized
__device__ __align__(128) float g_wt[CK_PAD * D_DIM];   // [30720][512] transposed, normalized,
                                                        // tf32-rounded; rows>=30000 stay 0
__device__ float  g_invw[CK];
__device__ float  g_arc_m[N_SAMP * NTILES_G];
__device__ float  g_arc_s[N_SAMP * NTILES_G];
__device__ float  g_lab[N_SAMP];
__device__ int    g_dap[N_SAMP];
__device__ int    g_dan[N_SAMP];
__device__ double g_arc_sum, g_tl_sum, g_center_sum;
__device__ int    g_nnz;

// ---------------- PTX helpers (sm_80-era, plain-target safe) ----------------
__device__ __forceinline__ uint32_t smem_u32(const void* p) {
    uint32_t a;
    asm("{ .reg .u64 t; cvta.to.shared.u64 t, %1; cvt.u32.u64 %0, t; }" : "=r"(a) : "l"(p));
    return a;
}
__device__ __forceinline__ void cp16(uint32_t dst, const void* src) {
    asm volatile("cp.async.cg.shared.global [%0], [%1], 16;" :: "r"(dst), "l"(src) : "memory");
}
#define CP_COMMIT() asm volatile("cp.async.commit_group;" ::: "memory")
#define CP_WAIT1()  asm volatile("cp.async.wait_group 1;" ::: "memory")

__device__ __forceinline__ void ldsm4(uint32_t* r, uint32_t addr) {
    asm volatile("ldmatrix.sync.aligned.m8n8.x4.shared.b16 {%0,%1,%2,%3}, [%4];"
        : "=r"(r[0]), "=r"(r[1]), "=r"(r[2]), "=r"(r[3]) : "r"(addr));
}
__device__ __forceinline__ void mma_tf32(float* d, const uint32_t* a, uint32_t b0, uint32_t b1) {
    asm volatile("mma.sync.aligned.m16n8k8.row.col.f32.tf32.tf32.f32 "
        "{%0,%1,%2,%3}, {%4,%5,%6,%7}, {%8,%9}, {%0,%1,%2,%3};"
        : "+f"(d[0]), "+f"(d[1]), "+f"(d[2]), "+f"(d[3])
        : "r"(a[0]), "r"(a[1]), "r"(a[2]), "r"(a[3]), "r"(b0), "r"(b1));
}
// tf32 destination must be a .b32 register (ptxas rejects f32 dst) — return bits.
__device__ __forceinline__ float to_tf32(float x) {
    uint32_t r;
    asm("cvt.rna.tf32.f32 %0, %1;" : "=r"(r) : "f"(x));
    return __uint_as_float(r);
}
__device__ __forceinline__ void lse_merge(float& M, float& S, float m2, float s2) {
    if (m2 > M) { S = S * expf(M - m2) + s2; M = m2; }
    else        { S += s2 * expf(m2 - M); }
}

// ---------------- prep kernels ----------------
__global__ void k_init() {
    int i = blockIdx.x * blockDim.x + threadIdx.x;
    if (i < N_SAMP) { g_dap[i] = __float_as_int(-1.0f); g_dan[i] = __float_as_int(3.0f); }
    if (i == 0) { g_arc_sum = 0.0; g_tl_sum = 0.0; g_center_sum = 0.0; g_nnz = 0; }
}

__global__ void k_norm_emb(const float* __restrict__ emb) {
    int row = blockIdx.x, tid = threadIdx.x;
    const float* src = emb + row * D_DIM;
    float s = 0.f;
    for (int d = tid; d < D_DIM; d += 256) { float v = src[d]; s += v * v; }
    __shared__ float red[256];
    red[tid] = s; __syncthreads();
    for (int st = 128; st > 0; st >>= 1) { if (tid < st) red[tid] += red[tid + st]; __syncthreads(); }
    float inv = 1.f / fmaxf(sqrtf(red[0]), 1e-12f);
    for (int d = tid; d < D_DIM; d += 256) {
        float v = src[d] * inv;
        g_e[row * D_DIM + d]  = v;
        g_et[row * D_DIM + d] = to_tf32(v);
    }
}

__global__ void k_wnorm(const float* __restrict__ W) {
    int j = blockIdx.x * blockDim.x + threadIdx.x;
    if (j >= CK) return;
    float s = 0.f;
    #pragma unroll 8
    for (int k = 0; k < D_DIM; k++) { float v = W[k * CK + j]; s += v * v; }
    g_invw[j] = 1.f / fmaxf(sqrtf(s), 1e-12f);
}

// transpose + normalize + tf32 round:  Wt[j][k] = tf32(W[k][j] * invw[j])
__global__ void k_wtrans(const float* __restrict__ W) {
    __shared__ float tile[32][33];
    int j0 = blockIdx.x * 32, k0 = blockIdx.y * 32;
    int tx = threadIdx.x, ty = threadIdx.y;
    #pragma unroll
    for (int i = 0; i < 32; i += 8) {
        int k = k0 + ty + i, j = j0 + tx;
        tile[ty + i][tx] = (j < CK) ? W[k * CK + j] : 0.f;
    }
    __syncthreads();
    #pragma unroll
    for (int i = 0; i < 32; i += 8) {
        int j = j0 + ty + i, k = k0 + tx;
        if (j < CK)
            g_wt[j * D_DIM + k] = to_tf32(tile[tx][ty + i] * g_invw[j]);
    }
}

// ============================================================================
// arc GEMM: 128x96 tile, 1-pass TF32 mma.sync, 3-stage cp.async, 1 sync/kc.
// SMEM rows 144B pitch (conflict-free fp32 ldmatrix).
// Stage: A 128*144=18432 | B 96*144=13824 -> 32256. 3 stages = 96768 (2 CTA/SM)
// ============================================================================
#define A_OFF_B  18432
#define A_STG    32256
#define A_SMEM   (3 * A_STG)       // epilogue reuses 51200

__device__ __forceinline__ void load_arc_stage(uint32_t st, int kc, int rowA, int colB, int tid) {
    int gk = kc * 32;
    #pragma unroll
    for (int i = 0; i < 4; i++) {               // A: 128 rows x 8 segs
        int idx = tid + i * 256;
        int row = idx >> 3, c = idx & 7;
        cp16(st + row * RP + c * 16, &g_et[(rowA + row) * D_DIM + gk + c * 4]);
    }
    #pragma unroll
    for (int i = 0; i < 3; i++) {               // B: 96 rows x 8 segs
        int idx = tid + i * 256;
        int row = idx >> 3, c = idx & 7;
        cp16(st + A_OFF_B + row * RP + c * 16, &g_wt[(colB + row) * D_DIM + gk + c * 4]);
    }
}

__global__ void __launch_bounds__(256) k_gemm_arc(const int* __restrict__ labels) {
    extern __shared__ char smem[];
    uint32_t sb = smem_u32(smem);
    int tid = threadIdx.x, wid = tid >> 5, lane = tid & 31;
    int warpM = wid & 3, warpN = wid >> 2;          // 4M x 2N
    int rowA = blockIdx.x * 128;
    int tileN = blockIdx.y;
    int colB = tileN * ABN;

    float acc[2][6][4];
    #pragma unroll
    for (int a = 0; a < 2; a++)
        #pragma unroll
        for (int b = 0; b < 6; b++)
            #pragma unroll
            for (int c = 0; c < 4; c++) acc[a][b][c] = 0.f;

    // tf32-via-ldmatrix addressing: matrices {rows0-7,rows8-15} x {cols0-3,cols4-7}
    int lrow = (lane & 7) + ((lane >> 3) & 1) * 8;
    int lcol = ((lane >> 4) & 1) * 16;
    uint32_t aoff[2], boff[3];
    #pragma unroll
    for (int mt = 0; mt < 2; mt++) aoff[mt] = (warpM * 32 + mt * 16 + lrow) * RP + lcol;
    #pragma unroll
    for (int bg = 0; bg < 3; bg++) boff[bg] = A_OFF_B + (warpN * 48 + bg * 16 + lrow) * RP + lcol;

    load_arc_stage(sb, 0, rowA, colB, tid); CP_COMMIT();
    load_arc_stage(sb + A_STG, 1, rowA, colB, tid); CP_COMMIT();

    #pragma unroll 1
    for (int kc = 0; kc < 16; kc++) {
        CP_WAIT1();
        __syncthreads();
        if (kc + 2 < 16)
            load_arc_stage(sb + ((kc + 2) % 3) * A_STG, kc + 2, rowA, colB, tid);
        CP_COMMIT();
        uint32_t st = sb + (kc % 3) * A_STG;
        #pragma unroll
        for (int ks = 0; ks < 4; ks++) {          // 4 x k8 = 32 K
            uint32_t ar[2][4], br[3][4];
            #pragma unroll
            for (int mt = 0; mt < 2; mt++) ldsm4(ar[mt], st + aoff[mt] + ks * 32);
            #pragma unroll
            for (int bg = 0; bg < 3; bg++) ldsm4(br[bg], st + boff[bg] + ks * 32);
            #pragma unroll
            for (int mt = 0; mt < 2; mt++)
                #pragma unroll
                for (int bg = 0; bg < 3; bg++) {
                    mma_tf32(acc[mt][bg * 2],     ar[mt], br[bg][0], br[bg][2]);
                    mma_tf32(acc[mt][bg * 2 + 1], ar[mt], br[bg][1], br[bg][3]);
                }
        }
    }

    // ---- epilogue: accum -> smem (pitch 100 fp32), fused subcenter/margin/lse ----
    __syncthreads();
    float* se = (float*)smem;
    #pragma unroll
    for (int mt = 0; mt < 2; mt++) {
        int r = warpM * 32 + mt * 16 + (lane >> 2);
        #pragma unroll
        for (int nt = 0; nt < 6; nt++) {
            int c = warpN * 48 + nt * 8 + ((lane & 3) << 1);
            se[r * 100 + c]           = acc[mt][nt][0];
            se[r * 100 + c + 1]       = acc[mt][nt][1];
            se[(r + 8) * 100 + c]     = acc[mt][nt][2];
            se[(r + 8) * 100 + c + 1] = acc[mt][nt][3];
        }
    }
    __syncthreads();

    int r = tid >> 1, h = tid & 1;
    int gi = rowA + r;
    int lab = labels[gi];
    int cbase = tileN * 32 + h * 16;
    const float* row = se + r * 100 + h * 48;
    float M = -1e30f, S = 0.f;
    #pragma unroll
    for (int g = 0; g < 16; g++) {
        int c = cbase + g;
        if (c >= C_CLS) break;
        float cm = fmaxf(fmaxf(row[3*g], row[3*g+1]), row[3*g+2]);
        float logit;
        if (c == lab) {
            float cc = fminf(fmaxf(cm, -1.f + 1e-7f), 1.f - 1e-7f);
            float sn = sqrtf(fmaxf(1.f - cc * cc, 0.f));
            logit = ARC_S * (cc * COS_M - sn * SIN_M);
            g_lab[gi] = logit;
        } else {
            logit = ARC_S * cm;
        }
        lse_merge(M, S, logit, 1.f);
    }
    float pM = __shfl_xor_sync(0xffffffffu, M, 1);
    float pS = __shfl_xor_sync(0xffffffffu, S, 1);
    lse_merge(M, S, pM, pS);
    if (h == 0) {
        g_arc_m[gi * NTILES_G + tileN] = M;
        g_arc_s[gi * NTILES_G + tileN] = S;
    }
}

__global__ void k_arc_reduce() {
    int row = blockIdx.x, tid = threadIdx.x;
    float M = -1e30f, S = 0.f;
    for (int t = tid; t < NTILES_G; t += 256)
        lse_merge(M, S, g_arc_m[row * NTILES_G + t], g_arc_s[row * NTILES_G + t]);
    __shared__ float sm[256], ss[256];
    sm[tid] = M; ss[tid] = S;
    __syncthreads();
    for (int st = 128; st > 0; st >>= 1) {
        if (tid < st) {
            float m1 = sm[tid], s1 = ss[tid];
            lse_merge(m1, s1, sm[tid + st], ss[tid + st]);
            sm[tid] = m1; ss[tid] = s1;
        }
        __syncthreads();
    }
    if (tid == 0) {
        float lse = sm[0] + logf(ss[0]);
        atomicAdd(&g_arc_sum, (double)(lse - g_lab[row]));
    }
}

// ============================================================================
// sim GEMM: 128x128, 1-pass TF32, 3-stage, fused triplet epilogue
// Stage: A 18432 | B 18432 -> 36864. 3 stages = 110592 (+labels)
// ============================================================================
#define S_OFF_B  18432
#define S_STG    36864
#define S_SMEM   (3 * S_STG + 512)

__device__ __forceinline__ void load_sim_stage(uint32_t st, int kc, int rowA, int colB, int tid) {
    int gk = kc * 32;
    #pragma unroll
    for (int i = 0; i < 4; i++) {
        int idx = tid + i * 256;
        int row = idx >> 3, c = idx & 7;
        cp16(st + row * RP + c * 16,           &g_et[(rowA + row) * D_DIM + gk + c * 4]);
        cp16(st + S_OFF_B + row * RP + c * 16, &g_et[(colB + row) * D_DIM + gk + c * 4]);
    }
}

__global__ void __launch_bounds__(256) k_gemm_sim(const int* __restrict__ labels) {
    extern __shared__ char smem[];
    uint32_t sb = smem_u32(smem);
    int tid = threadIdx.x, wid = tid >> 5, lane = tid & 31;
    int warpM = wid & 3, warpN = wid >> 2;          // 4M x 2N
    int rowA = blockIdx.x * 128;
    int colB = blockIdx.y * 128;

    int* slab = (int*)(smem + 3 * S_STG);
    if (tid < 128) slab[tid] = labels[colB + tid];

    float acc[2][8][4];
    #pragma unroll
    for (int a = 0; a < 2; a++)
        #pragma unroll
        for (int b = 0; b < 8; b++)
            #pragma unroll
            for (int c = 0; c < 4; c++) acc[a][b][c] = 0.f;

    int lrow = (lane & 7) + ((lane >> 3) & 1) * 8;
    int lcol = ((lane >> 4) & 1) * 16;
    uint32_t aoff[2], boff[4];
    #pragma unroll
    for (int mt = 0; mt < 2; mt++) aoff[mt] = (warpM * 32 + mt * 16 + lrow) * RP + lcol;
    #pragma unroll
    for (int bg = 0; bg < 4; bg++) boff[bg] = S_OFF_B + (warpN * 64 + bg * 16 + lrow) * RP + lcol;

    load_sim_stage(sb, 0, rowA, colB, tid); CP_COMMIT();
    load_sim_stage(sb + S_STG, 1, rowA, colB, tid); CP_COMMIT();

    #pragma unroll 1
    for (int kc = 0; kc < 16; kc++) {
        CP_WAIT1();
        __syncthreads();
        if (kc + 2 < 16)
            load_sim_stage(sb + ((kc + 2) % 3) * S_STG, kc + 2, rowA, colB, tid);
        CP_COMMIT();
        uint32_t st = sb + (kc % 3) * S_STG;
        #pragma unroll
        for (int ks = 0; ks < 4; ks++) {
            uint32_t ar[2][4], br[4][4];
            #pragma unroll
            for (int mt = 0; mt < 2; mt++) ldsm4(ar[mt], st + aoff[mt] + ks * 32);
            #pragma unroll
            for (int bg = 0; bg < 4; bg++) ldsm4(br[bg], st + boff[bg] + ks * 32);
            #pragma unroll
            for (int mt = 0; mt < 2; mt++)
                #pragma unroll
                for (int bg = 0; bg < 4; bg++) {
                    mma_tf32(acc[mt][bg * 2],     ar[mt], br[bg][0], br[bg][2]);
                    mma_tf32(acc[mt][bg * 2 + 1], ar[mt], br[bg][1], br[bg][3]);
                }
        }
    }

    // ---- fused triplet epilogue ----
    #pragma unroll
    for (int mt = 0; mt < 2; mt++) {
        #pragma unroll
        for (int ro = 0; ro < 2; ro++) {
            int r = warpM * 32 + mt * 16 + (lane >> 2) + ro * 8;
            int gi = rowA + r;
            int myl = __ldg(&labels[gi]);
            float dap = -1.f, dan = 3.f;
            #pragma unroll
            for (int nt = 0; nt < 8; nt++) {
                #pragma unroll
                for (int j = 0; j < 2; j++) {
                    int cl = warpN * 64 + nt * 8 + ((lane & 3) << 1) + j;
                    int gj = colB + cl;
                    float sim  = acc[mt][nt][ro * 2 + j];
                    float dist = sqrtf(fmaxf(2.f - 2.f * sim, 0.f));
                    if (slab[cl] == myl) { if (gj != gi) dap = fmaxf(dap, dist); }
                    else                 { dan = fminf(dan, dist); }
                }
            }
            #pragma unroll
            for (int off = 1; off < 4; off <<= 1) {
                dap = fmaxf(dap, __shfl_xor_sync(0xffffffffu, dap, off));
                dan = fminf(dan, __shfl_xor_sync(0xffffffffu, dan, off));
            }
            if ((lane & 3) == 0) {
                atomicMax(&g_dap[gi], __float_as_int(dap));
                atomicMin(&g_dan[gi], __float_as_int(dan));
            }
        }
    }
}

__global__ void k_trip_final() {
    int i = blockIdx.x * blockDim.x + threadIdx.x;
    if (i >= N_SAMP) return;
    float dap = __int_as_float(g_dap[i]);
    float dan = __int_as_float(g_dan[i]);
    bool valid = (dap >= 0.f) && (dan < 2.5f);
    float tl = valid ? fmaxf(dap - dan + TRIP_M, 0.f) : 0.f;
    if (tl > 0.f) {
        atomicAdd(&g_tl_sum, (double)tl);
        atomicAdd(&g_nnz, 1);
    }
}

__global__ void k_center(const int* __restrict__ labels, const float* __restrict__ centers) {
    int row = blockIdx.x, tid = threadIdx.x;
    int lab = labels[row];
    const float* c = centers + lab * D_DIM;
    const float* e = g_e + row * D_DIM;
    float s = 0.f;
    for (int d = tid; d < D_DIM; d += 256) { float diff = e[d] - c[d]; s += diff * diff; }
    __shared__ float red[256];
    red[tid] = s; __syncthreads();
    for (int st = 128; st > 0; st >>= 1) { if (tid < st) red[tid] += red[tid + st]; __syncthreads(); }
    if (tid == 0) atomicAdd(&g_center_sum, (double)red[0]);
}

__global__ void k_final(float* __restrict__ out) {
    double arc  = g_arc_sum / (double)N_SAMP;
    int    nnz  = g_nnz > 1 ? g_nnz : 1;
    double trip = g_tl_sum / (double)nnz;
    double cen  = g_center_sum / (double)N_SAMP;
    out[0] = (float)(arc + 0.5 * trip + 0.01 * cen);
}

// ---------------- launch ----------------
extern "C" void kernel_launch(void* const* d_in, const int* in_sizes, int n_in,
                              void* d_out, int out_size) {
    const float* emb     = (const float*)d_in[0];
    const int*   labels  = (const int*)  d_in[1];
    const float* W       = (const float*)d_in[2];
    const float* centers = (const float*)d_in[3];
    float* out = (float*)d_out;

    cudaFuncSetAttribute(k_gemm_arc, cudaFuncAttributeMaxDynamicSharedMemorySize, A_SMEM);
    cudaFuncSetAttribute(k_gemm_sim, cudaFuncAttributeMaxDynamicSharedMemorySize, S_SMEM);

    k_init<<<2, 1024>>>();
    k_norm_emb<<<N_SAMP, 256>>>(emb);
    k_wnorm<<<(CK + 255) / 256, 256>>>(W);
    k_wtrans<<<dim3((CK + 31) / 32, D_DIM / 32), dim3(32, 8)>>>(W);

    k_gemm_arc<<<dim3(16, NTILES_G), 256, A_SMEM>>>(labels);
    k_arc_reduce<<<N_SAMP, 256>>>();

    k_gemm_sim<<<dim3(16, 16), 256, S_SMEM>>>(labels);
    k_trip_final<<<8, 256>>>();

    k_center<<<N_SAMP, 256>>>(labels, centers);
    k_final<<<1, 1>>>(out);
}

// round 9
// speedup vs baseline: 2.3741x; 1.5504x over previous
#include <cuda_runtime.h>
#include <cuda_fp16.h>
#include <math.h>
#include <stdint.h>

// ---------------- problem constants ----------------
#define N_SAMP 2048
#define D_DIM  512
#define C_CLS  10000
#define CK     30000
#define CK_PAD 30720
#define ARC_S  30.0f
#define COS_M  0.9210609940028851f   // cos(0.4)
#define SIN_M  0.3894183423086505f   // sin(0.4)
#define TRIP_M 0.3f

#define ABN      96                  // arc tile N (32 classes)
#define NTILES_G 313                 // ceil(30000/96) -> cols < 30048 (zero-padded)
#define RP       144                 // sim SMEM row pitch bytes (32 fp32 + 4 pad)

// ---------------- scratch ----------------
__device__ __align__(128) float  g_e[N_SAMP * D_DIM];   // exact normalized (center loss)
__device__ __align__(128) float  g_et[N_SAMP * D_DIM];  // tf32-rounded normalized (sim)
__device__ __align__(128) __half g_eh[N_SAMP * D_DIM];  // fp16 normalized (arc A)
__device__ __align__(128) __half g_wth[CK_PAD * D_DIM]; // fp16 transposed normalized W (arc B);
                                                        // rows >= 30000 stay zero
__device__ float  g_invw[CK];
__device__ float  g_arc_m[N_SAMP * NTILES_G];
__device__ float  g_arc_s[N_SAMP * NTILES_G];
__device__ float  g_lab[N_SAMP];
__device__ int    g_dap[N_SAMP];
__device__ int    g_dan[N_SAMP];
__device__ double g_arc_sum, g_tl_sum, g_center_sum;
__device__ int    g_nnz;

// ---------------- PTX helpers (sm_80-era, plain-target safe) ----------------
__device__ __forceinline__ uint32_t smem_u32(const void* p) {
    uint32_t a;
    asm("{ .reg .u64 t; cvta.to.shared.u64 t, %1; cvt.u32.u64 %0, t; }" : "=r"(a) : "l"(p));
    return a;
}
__device__ __forceinline__ void cp16(uint32_t dst, const void* src) {
    asm volatile("cp.async.cg.shared.global [%0], [%1], 16;" :: "r"(dst), "l"(src) : "memory");
}
#define CP_COMMIT() asm volatile("cp.async.commit_group;" ::: "memory")
#define CP_WAIT1()  asm volatile("cp.async.wait_group 1;" ::: "memory")

__device__ __forceinline__ void ldsm4(uint32_t* r, uint32_t addr) {
    asm volatile("ldmatrix.sync.aligned.m8n8.x4.shared.b16 {%0,%1,%2,%3}, [%4];"
        : "=r"(r[0]), "=r"(r[1]), "=r"(r[2]), "=r"(r[3]) : "r"(addr));
}
__device__ __forceinline__ void mma_fp16(float* d, const uint32_t* a, uint32_t b0, uint32_t b1) {
    asm volatile("mma.sync.aligned.m16n8k16.row.col.f32.f16.f16.f32 "
        "{%0,%1,%2,%3}, {%4,%5,%6,%7}, {%8,%9}, {%0,%1,%2,%3};"
        : "+f"(d[0]), "+f"(d[1]), "+f"(d[2]), "+f"(d[3])
        : "r"(a[0]), "r"(a[1]), "r"(a[2]), "r"(a[3]), "r"(b0), "r"(b1));
}
__device__ __forceinline__ void mma_tf32(float* d, const uint32_t* a, uint32_t b0, uint32_t b1) {
    asm volatile("mma.sync.aligned.m16n8k8.row.col.f32.tf32.tf32.f32 "
        "{%0,%1,%2,%3}, {%4,%5,%6,%7}, {%8,%9}, {%0,%1,%2,%3};"
        : "+f"(d[0]), "+f"(d[1]), "+f"(d[2]), "+f"(d[3])
        : "r"(a[0]), "r"(a[1]), "r"(a[2]), "r"(a[3]), "r"(b0), "r"(b1));
}
// tf32 cvt needs a .b32 destination register
__device__ __forceinline__ float to_tf32(float x) {
    uint32_t r;
    asm("cvt.rna.tf32.f32 %0, %1;" : "=r"(r) : "f"(x));
    return __uint_as_float(r);
}
__device__ __forceinline__ void lse_merge(float& M, float& S, float m2, float s2) {
    if (m2 > M) { S = S * expf(M - m2) + s2; M = m2; }
    else        { S += s2 * expf(m2 - M); }
}

// ---------------- prep kernels ----------------
__global__ void k_init() {
    int i = blockIdx.x * blockDim.x + threadIdx.x;
    if (i < N_SAMP) { g_dap[i] = __float_as_int(-1.0f); g_dan[i] = __float_as_int(3.0f); }
    if (i == 0) { g_arc_sum = 0.0; g_tl_sum = 0.0; g_center_sum = 0.0; g_nnz = 0; }
}

__global__ void k_norm_emb(const float* __restrict__ emb) {
    int row = blockIdx.x, tid = threadIdx.x;
    const float* src = emb + row * D_DIM;
    float s = 0.f;
    for (int d = tid; d < D_DIM; d += 256) { float v = src[d]; s += v * v; }
    __shared__ float red[256];
    red[tid] = s; __syncthreads();
    for (int st = 128; st > 0; st >>= 1) { if (tid < st) red[tid] += red[tid + st]; __syncthreads(); }
    float inv = 1.f / fmaxf(sqrtf(red[0]), 1e-12f);
    for (int d = tid; d < D_DIM; d += 256) {
        float v = src[d] * inv;
        g_e[row * D_DIM + d]  = v;
        g_et[row * D_DIM + d] = to_tf32(v);
        g_eh[row * D_DIM + d] = __float2half_rn(v);
    }
}

__global__ void k_wnorm(const float* __restrict__ W) {
    int j = blockIdx.x * blockDim.x + threadIdx.x;
    if (j >= CK) return;
    float s = 0.f;
    #pragma unroll 8
    for (int k = 0; k < D_DIM; k++) { float v = W[k * CK + j]; s += v * v; }
    g_invw[j] = 1.f / fmaxf(sqrtf(s), 1e-12f);
}

// transpose + normalize + fp16 round:  Wt[j][k] = half(W[k][j] * invw[j])
__global__ void k_wtrans(const float* __restrict__ W) {
    __shared__ float tile[32][33];
    int j0 = blockIdx.x * 32, k0 = blockIdx.y * 32;
    int tx = threadIdx.x, ty = threadIdx.y;
    #pragma unroll
    for (int i = 0; i < 32; i += 8) {
        int k = k0 + ty + i, j = j0 + tx;
        tile[ty + i][tx] = (j < CK) ? W[k * CK + j] : 0.f;
    }
    __syncthreads();
    #pragma unroll
    for (int i = 0; i < 32; i += 8) {
        int j = j0 + ty + i, k = k0 + tx;
        if (j < CK)
            g_wth[j * D_DIM + k] = __float2half_rn(tile[tx][ty + i] * g_invw[j]);
    }
}

// ============================================================================
// arc GEMM: 128x96 tile, SINGLE-PASS fp16 m16n8k16, 3-stage cp.async, 1 sync/kc
// SMEM rows 80B pitch (32 halfs = 64B + 16B pad -> conflict-free ldmatrix).
// Stage: A 128*80=10240 | B 96*80=7680 -> 17920. 3 stages = 53760 (2 CTA/SM)
// ============================================================================
#define A_OFF_B  10240
#define A_STG    17920
#define A_SMEM   (3 * A_STG)       // 53760 >= epilogue 51200

__device__ __forceinline__ void load_arc_stage(uint32_t st, int kc, int rowA, int colB, int tid) {
    int gk = kc * 32;
    #pragma unroll
    for (int i = 0; i < 2; i++) {               // A: 128 rows x 4 segs of 16B
        int idx = tid + i * 256;
        int row = idx >> 2, c = idx & 3;
        cp16(st + row * 80 + c * 16, &g_eh[(rowA + row) * D_DIM + gk + c * 8]);
    }
    {                                           // B rows 0..63
        int row = tid >> 2, c = tid & 3;
        cp16(st + A_OFF_B + row * 80 + c * 16, &g_wth[(colB + row) * D_DIM + gk + c * 8]);
    }
    if (tid < 128) {                            // B rows 64..95
        int idx = tid + 256;
        int row = idx >> 2, c = idx & 3;
        cp16(st + A_OFF_B + row * 80 + c * 16, &g_wth[(colB + row) * D_DIM + gk + c * 8]);
    }
}

__global__ void __launch_bounds__(256) k_gemm_arc(const int* __restrict__ labels) {
    extern __shared__ char smem[];
    uint32_t sb = smem_u32(smem);
    int tid = threadIdx.x, wid = tid >> 5, lane = tid & 31;
    int warpM = wid & 3, warpN = wid >> 2;          // 4M x 2N
    int rowA = blockIdx.x * 128;
    int tileN = blockIdx.y;
    int colB = tileN * ABN;

    float acc[2][6][4];
    #pragma unroll
    for (int a = 0; a < 2; a++)
        #pragma unroll
        for (int b = 0; b < 6; b++)
            #pragma unroll
            for (int c = 0; c < 4; c++) acc[a][b][c] = 0.f;

    int lrow = lane & 15, lhalf = lane >> 4;
    uint32_t aoff[2], boff[3];
    #pragma unroll
    for (int mt = 0; mt < 2; mt++) aoff[mt] = (warpM * 32 + mt * 16 + lrow) * 80 + lhalf * 16;
    #pragma unroll
    for (int bg = 0; bg < 3; bg++) boff[bg] = A_OFF_B + (warpN * 48 + bg * 16 + lrow) * 80 + lhalf * 16;

    load_arc_stage(sb, 0, rowA, colB, tid); CP_COMMIT();
    load_arc_stage(sb + A_STG, 1, rowA, colB, tid); CP_COMMIT();

    #pragma unroll 1
    for (int kc = 0; kc < 16; kc++) {
        CP_WAIT1();
        __syncthreads();
        if (kc + 2 < 16)
            load_arc_stage(sb + ((kc + 2) % 3) * A_STG, kc + 2, rowA, colB, tid);
        CP_COMMIT();
        uint32_t st = sb + (kc % 3) * A_STG;
        #pragma unroll
        for (int ks = 0; ks < 2; ks++) {          // 2 x k16 = 32 K
            uint32_t ar[2][4], br[3][4];
            #pragma unroll
            for (int mt = 0; mt < 2; mt++) ldsm4(ar[mt], st + aoff[mt] + ks * 32);
            #pragma unroll
            for (int bg = 0; bg < 3; bg++) ldsm4(br[bg], st + boff[bg] + ks * 32);
            #pragma unroll
            for (int mt = 0; mt < 2; mt++)
                #pragma unroll
                for (int nt = 0; nt < 6; nt++) {
                    int bt = nt >> 1, sel = nt & 1;
                    mma_fp16(acc[mt][nt], ar[mt], br[bt][sel], br[bt][sel | 2]);
                }
        }
    }

    // ---- epilogue: accum -> smem (pitch 100 fp32), fused subcenter/margin/lse ----
    __syncthreads();
    float* se = (float*)smem;
    #pragma unroll
    for (int mt = 0; mt < 2; mt++) {
        int r = warpM * 32 + mt * 16 + (lane >> 2);
        #pragma unroll
        for (int nt = 0; nt < 6; nt++) {
            int c = warpN * 48 + nt * 8 + ((lane & 3) << 1);
            se[r * 100 + c]           = acc[mt][nt][0];
            se[r * 100 + c + 1]       = acc[mt][nt][1];
            se[(r + 8) * 100 + c]     = acc[mt][nt][2];
            se[(r + 8) * 100 + c + 1] = acc[mt][nt][3];
        }
    }
    __syncthreads();

    int r = tid >> 1, h = tid & 1;
    int gi = rowA + r;
    int lab = labels[gi];
    int cbase = tileN * 32 + h * 16;
    const float* row = se + r * 100 + h * 48;
    float M = -1e30f, S = 0.f;
    #pragma unroll
    for (int g = 0; g < 16; g++) {
        int c = cbase + g;
        if (c >= C_CLS) break;
        float cm = fmaxf(fmaxf(row[3*g], row[3*g+1]), row[3*g+2]);
        float logit;
        if (c == lab) {
            float cc = fminf(fmaxf(cm, -1.f + 1e-7f), 1.f - 1e-7f);
            float sn = sqrtf(fmaxf(1.f - cc * cc, 0.f));
            logit = ARC_S * (cc * COS_M - sn * SIN_M);
            g_lab[gi] = logit;
        } else {
            logit = ARC_S * cm;
        }
        lse_merge(M, S, logit, 1.f);
    }
    float pM = __shfl_xor_sync(0xffffffffu, M, 1);
    float pS = __shfl_xor_sync(0xffffffffu, S, 1);
    lse_merge(M, S, pM, pS);
    if (h == 0) {
        g_arc_m[gi * NTILES_G + tileN] = M;
        g_arc_s[gi * NTILES_G + tileN] = S;
    }
}

__global__ void k_arc_reduce() {
    int row = blockIdx.x, tid = threadIdx.x;
    float M = -1e30f, S = 0.f;
    for (int t = tid; t < NTILES_G; t += 256)
        lse_merge(M, S, g_arc_m[row * NTILES_G + t], g_arc_s[row * NTILES_G + t]);
    __shared__ float sm[256], ss[256];
    sm[tid] = M; ss[tid] = S;
    __syncthreads();
    for (int st = 128; st > 0; st >>= 1) {
        if (tid < st) {
            float m1 = sm[tid], s1 = ss[tid];
            lse_merge(m1, s1, sm[tid + st], ss[tid + st]);
            sm[tid] = m1; ss[tid] = s1;
        }
        __syncthreads();
    }
    if (tid == 0) {
        float lse = sm[0] + logf(ss[0]);
        atomicAdd(&g_arc_sum, (double)(lse - g_lab[row]));
    }
}

// ============================================================================
// sim GEMM: 128x128, 1-pass TF32 (precision insurance for triplet argmin/argmax),
// 3-stage, fused triplet epilogue. Stage: A 18432 | B 18432 -> 36864
// ============================================================================
#define S_OFF_B  18432
#define S_STG    36864
#define S_SMEM   (3 * S_STG + 512)

__device__ __forceinline__ void load_sim_stage(uint32_t st, int kc, int rowA, int colB, int tid) {
    int gk = kc * 32;
    #pragma unroll
    for (int i = 0; i < 4; i++) {
        int idx = tid + i * 256;
        int row = idx >> 3, c = idx & 7;
        cp16(st + row * RP + c * 16,           &g_et[(rowA + row) * D_DIM + gk + c * 4]);
        cp16(st + S_OFF_B + row * RP + c * 16, &g_et[(colB + row) * D_DIM + gk + c * 4]);
    }
}

__global__ void __launch_bounds__(256) k_gemm_sim(const int* __restrict__ labels) {
    extern __shared__ char smem[];
    uint32_t sb = smem_u32(smem);
    int tid = threadIdx.x, wid = tid >> 5, lane = tid & 31;
    int warpM = wid & 3, warpN = wid >> 2;          // 4M x 2N
    int rowA = blockIdx.x * 128;
    int colB = blockIdx.y * 128;

    int* slab = (int*)(smem + 3 * S_STG);
    if (tid < 128) slab[tid] = labels[colB + tid];

    float acc[2][8][4];
    #pragma unroll
    for (int a = 0; a < 2; a++)
        #pragma unroll
        for (int b = 0; b < 8; b++)
            #pragma unroll
            for (int c = 0; c < 4; c++) acc[a][b][c] = 0.f;

    int lrow = (lane & 7) + ((lane >> 3) & 1) * 8;
    int lcol = ((lane >> 4) & 1) * 16;
    uint32_t aoff[2], boff[4];
    #pragma unroll
    for (int mt = 0; mt < 2; mt++) aoff[mt] = (warpM * 32 + mt * 16 + lrow) * RP + lcol;
    #pragma unroll
    for (int bg = 0; bg < 4; bg++) boff[bg] = S_OFF_B + (warpN * 64 + bg * 16 + lrow) * RP + lcol;

    load_sim_stage(sb, 0, rowA, colB, tid); CP_COMMIT();
    load_sim_stage(sb + S_STG, 1, rowA, colB, tid); CP_COMMIT();

    #pragma unroll 1
    for (int kc = 0; kc < 16; kc++) {
        CP_WAIT1();
        __syncthreads();
        if (kc + 2 < 16)
            load_sim_stage(sb + ((kc + 2) % 3) * S_STG, kc + 2, rowA, colB, tid);
        CP_COMMIT();
        uint32_t st = sb + (kc % 3) * S_STG;
        #pragma unroll
        for (int ks = 0; ks < 4; ks++) {
            uint32_t ar[2][4], br[4][4];
            #pragma unroll
            for (int mt = 0; mt < 2; mt++) ldsm4(ar[mt], st + aoff[mt] + ks * 32);
            #pragma unroll
            for (int bg = 0; bg < 4; bg++) ldsm4(br[bg], st + boff[bg] + ks * 32);
            #pragma unroll
            for (int mt = 0; mt < 2; mt++)
                #pragma unroll
                for (int bg = 0; bg < 4; bg++) {
                    mma_tf32(acc[mt][bg * 2],     ar[mt], br[bg][0], br[bg][2]);
                    mma_tf32(acc[mt][bg * 2 + 1], ar[mt], br[bg][1], br[bg][3]);
                }
        }
    }

    // ---- fused triplet epilogue ----
    #pragma unroll
    for (int mt = 0; mt < 2; mt++) {
        #pragma unroll
        for (int ro = 0; ro < 2; ro++) {
            int r = warpM * 32 + mt * 16 + (lane >> 2) + ro * 8;
            int gi = rowA + r;
            int myl = __ldg(&labels[gi]);
            float dap = -1.f, dan = 3.f;
            #pragma unroll
            for (int nt = 0; nt < 8; nt++) {
                #pragma unroll
                for (int j = 0; j < 2; j++) {
                    int cl = warpN * 64 + nt * 8 + ((lane & 3) << 1) + j;
                    int gj = colB + cl;
                    float sim  = acc[mt][nt][ro * 2 + j];
                    float dist = sqrtf(fmaxf(2.f - 2.f * sim, 0.f));
                    if (slab[cl] == myl) { if (gj != gi) dap = fmaxf(dap, dist); }
                    else                 { dan = fminf(dan, dist); }
                }
            }
            #pragma unroll
            for (int off = 1; off < 4; off <<= 1) {
                dap = fmaxf(dap, __shfl_xor_sync(0xffffffffu, dap, off));
                dan = fminf(dan, __shfl_xor_sync(0xffffffffu, dan, off));
            }
            if ((lane & 3) == 0) {
                atomicMax(&g_dap[gi], __float_as_int(dap));
                atomicMin(&g_dan[gi], __float_as_int(dan));
            }
        }
    }
}

__global__ void k_trip_final() {
    int i = blockIdx.x * blockDim.x + threadIdx.x;
    if (i >= N_SAMP) return;
    float dap = __int_as_float(g_dap[i]);
    float dan = __int_as_float(g_dan[i]);
    bool valid = (dap >= 0.f) && (dan < 2.5f);
    float tl = valid ? fmaxf(dap - dan + TRIP_M, 0.f) : 0.f;
    if (tl > 0.f) {
        atomicAdd(&g_tl_sum, (double)tl);
        atomicAdd(&g_nnz, 1);
    }
}

__global__ void k_center(const int* __restrict__ labels, const float* __restrict__ centers) {
    int row = blockIdx.x, tid = threadIdx.x;
    int lab = labels[row];
    const float* c = centers + lab * D_DIM;
    const float* e = g_e + row * D_DIM;
    float s = 0.f;
    for (int d = tid; d < D_DIM; d += 256) { float diff = e[d] - c[d]; s += diff * diff; }
    __shared__ float red[256];
    red[tid] = s; __syncthreads();
    for (int st = 128; st > 0; st >>= 1) { if (tid < st) red[tid] += red[tid + st]; __syncthreads(); }
    if (tid == 0) atomicAdd(&g_center_sum, (double)red[0]);
}

__global__ void k_final(float* __restrict__ out) {
    double arc  = g_arc_sum / (double)N_SAMP;
    int    nnz  = g_nnz > 1 ? g_nnz : 1;
    double trip = g_tl_sum / (double)nnz;
    double cen  = g_center_sum / (double)N_SAMP;
    out[0] = (float)(arc + 0.5 * trip + 0.01 * cen);
}

// ---------------- launch ----------------
extern "C" void kernel_launch(void* const* d_in, const int* in_sizes, int n_in,
                              void* d_out, int out_size) {
    const float* emb     = (const float*)d_in[0];
    const int*   labels  = (const int*)  d_in[1];
    const float* W       = (const float*)d_in[2];
    const float* centers = (const float*)d_in[3];
    float* out = (float*)d_out;

    cudaFuncSetAttribute(k_gemm_arc, cudaFuncAttributeMaxDynamicSharedMemorySize, A_SMEM);
    cudaFuncSetAttribute(k_gemm_sim, cudaFuncAttributeMaxDynamicSharedMemorySize, S_SMEM);

    k_init<<<2, 1024>>>();
    k_norm_emb<<<N_SAMP, 256>>>(emb);
    k_wnorm<<<(CK + 255) / 256, 256>>>(W);
    k_wtrans<<<dim3((CK + 31) / 32, D_DIM / 32), dim3(32, 8)>>>(W);

    k_gemm_arc<<<dim3(16, NTILES_G), 256, A_SMEM>>>(labels);
    k_arc_reduce<<<N_SAMP, 256>>>();

    k_gemm_sim<<<dim3(16, 16), 256, S_SMEM>>>(labels);
    k_trip_final<<<8, 256>>>();

    k_center<<<N_SAMP, 256>>>(labels, centers);
    k_final<<<1, 1>>>(out);
}

// round 10
// speedup vs baseline: 2.6769x; 1.1276x over previous
#include <cuda_runtime.h>
#include <cuda_fp16.h>
#include <math.h>
#include <stdint.h>

// ---------------- problem constants ----------------
#define N_SAMP 2048
#define D_DIM  512
#define C_CLS  10000
#define CK     30000
#define CK_PAD 30720
#define ARC_S  30.0f
#define COS_M  0.9210609940028851f   // cos(0.4)
#define SIN_M  0.3894183423086505f   // sin(0.4)
#define TRIP_M 0.3f

#define ABN      96                  // arc tile N (32 classes)
#define NTILES_G 313                 // ceil(30000/96) -> cols < 30048 (zero-padded)
#define ARC_BLKS (16 * NTILES_G)     // 5008
#define SIM_BLKS 256                 // 16 x 16
#define ALL_BLKS (ARC_BLKS + SIM_BLKS)

// ---------------- scratch ----------------
__device__ __align__(128) float  g_e[N_SAMP * D_DIM];   // exact normalized (center loss)
__device__ __align__(128) __half g_eh[N_SAMP * D_DIM];  // fp16 normalized (both GEMMs)
__device__ __align__(128) __half g_wth[CK_PAD * D_DIM]; // fp16 transposed normalized W;
                                                        // rows >= 30000 never written (stay 0)
__device__ float  g_arc_m[N_SAMP * NTILES_G];
__device__ float  g_arc_s[N_SAMP * NTILES_G];
__device__ float  g_lab[N_SAMP];
__device__ int    g_dap[N_SAMP];
__device__ int    g_dan[N_SAMP];
__device__ double g_arc_sum, g_center_sum;

// ---------------- PTX helpers (sm_80-era, plain-target safe) ----------------
__device__ __forceinline__ uint32_t smem_u32(const void* p) {
    uint32_t a;
    asm("{ .reg .u64 t; cvta.to.shared.u64 t, %1; cvt.u32.u64 %0, t; }" : "=r"(a) : "l"(p));
    return a;
}
__device__ __forceinline__ void cp16(uint32_t dst, const void* src) {
    asm volatile("cp.async.cg.shared.global [%0], [%1], 16;" :: "r"(dst), "l"(src) : "memory");
}
#define CP_COMMIT() asm volatile("cp.async.commit_group;" ::: "memory")
#define CP_WAIT1()  asm volatile("cp.async.wait_group 1;" ::: "memory")

__device__ __forceinline__ void ldsm4(uint32_t* r, uint32_t addr) {
    asm volatile("ldmatrix.sync.aligned.m8n8.x4.shared.b16 {%0,%1,%2,%3}, [%4];"
        : "=r"(r[0]), "=r"(r[1]), "=r"(r[2]), "=r"(r[3]) : "r"(addr));
}
__device__ __forceinline__ void mma_fp16(float* d, const uint32_t* a, uint32_t b0, uint32_t b1) {
    asm volatile("mma.sync.aligned.m16n8k16.row.col.f32.f16.f16.f32 "
        "{%0,%1,%2,%3}, {%4,%5,%6,%7}, {%8,%9}, {%0,%1,%2,%3};"
        : "+f"(d[0]), "+f"(d[1]), "+f"(d[2]), "+f"(d[3])
        : "r"(a[0]), "r"(a[1]), "r"(a[2]), "r"(a[3]), "r"(b0), "r"(b1));
}
__device__ __forceinline__ void lse_merge(float& M, float& S, float m2, float s2) {
    if (m2 > M) { S = S * expf(M - m2) + s2; M = m2; }
    else        { S += s2 * expf(m2 - M); }
}

// ---------------- norm_emb (+ per-row init, + global sums zero) ----------------
__global__ void k_norm_emb(const float* __restrict__ emb) {
    int row = blockIdx.x, tid = threadIdx.x;
    if (tid == 0) {
        g_dap[row] = __float_as_int(-1.0f);
        g_dan[row] = __float_as_int(3.0f);
        if (row == 0) { g_arc_sum = 0.0; g_center_sum = 0.0; }
    }
    const float* src = emb + row * D_DIM;
    float s = 0.f;
    for (int d = tid; d < D_DIM; d += 256) { float v = src[d]; s += v * v; }
    __shared__ float red[256];
    red[tid] = s; __syncthreads();
    for (int st = 128; st > 0; st >>= 1) { if (tid < st) red[tid] += red[tid + st]; __syncthreads(); }
    float inv = 1.f / fmaxf(sqrtf(red[0]), 1e-12f);
    for (int d = tid; d < D_DIM; d += 256) {
        float v = src[d] * inv;
        g_e[row * D_DIM + d]  = v;
        g_eh[row * D_DIM + d] = __float2half_rn(v);
    }
}

// ---------------- fused W prep: norm + transpose + fp16, W read ONCE ----------
// block = 256 thr (8 warps), handles 32 columns x all 512 k.
// dyn smem: values [512][33] fp32 = 67584 B
__global__ void k_wprep(const float* __restrict__ W) {
    extern __shared__ char smem[];
    float* sv = (float*)smem;                 // [k][j] pitch 33
    __shared__ float part[8][32];
    __shared__ float sinv[32];
    int tid = threadIdx.x, w = tid >> 5, l = tid & 31;
    int j0 = blockIdx.x * 32;
    int j  = j0 + l;
    bool ok = j < CK;

    float s = 0.f;
    int kbase = w * 64;
    #pragma unroll 8
    for (int kk = 0; kk < 64; kk++) {
        int k = kbase + kk;
        float v = ok ? W[k * CK + j] : 0.f;
        sv[k * 33 + l] = v;
        s += v * v;
    }
    part[w][l] = s;
    __syncthreads();
    if (w == 0) {
        float t = 0.f;
        #pragma unroll
        for (int r = 0; r < 8; r++) t += part[r][l];
        sinv[l] = 1.f / fmaxf(sqrtf(t), 1e-12f);
    }
    __syncthreads();

    // write transposed fp16: warp w -> j-rows w*4 .. w*4+3
    #pragma unroll
    for (int rr = 0; rr < 4; rr++) {
        int jl = w * 4 + rr, jg = j0 + jl;
        if (jg >= CK) continue;
        float inv = sinv[jl];
        #pragma unroll
        for (int it = 0; it < 8; it++) {
            int k = it * 64 + l * 2;
            float v0 = sv[k * 33 + jl] * inv;
            float v1 = sv[(k + 1) * 33 + jl] * inv;
            *(__half2*)&g_wth[jg * D_DIM + k] = __floats2half2_rn(v0, v1);
        }
    }
}

// ============================================================================
// fused GEMM kernel: blocks [0, 5008) = arc 128x96, blocks [5008, 5264) = sim 128x128
// Both single-pass fp16 m16n8k16, 3-stage cp.async, 80B-pitch SMEM rows.
// arc stage 17920 (A 10240 | B 7680); sim stage 20480 (A 10240 | B 10240)
// SMEM = 3*20480 + 512 = 61952 -> 2 CTA/SM
// ============================================================================
#define A_OFF_B  10240
#define A_STG    17920
#define S_OFF_B  10240
#define S_STG    20480
#define G_SMEM   (3 * S_STG + 512)

__device__ __forceinline__ void load_arc_stage(uint32_t st, int kc, int rowA, int colB, int tid) {
    int gk = kc * 32;
    #pragma unroll
    for (int i = 0; i < 2; i++) {               // A: 128 rows x 4 segs of 16B
        int idx = tid + i * 256;
        int row = idx >> 2, c = idx & 3;
        cp16(st + row * 80 + c * 16, &g_eh[(rowA + row) * D_DIM + gk + c * 8]);
    }
    {                                           // B rows 0..63
        int row = tid >> 2, c = tid & 3;
        cp16(st + A_OFF_B + row * 80 + c * 16, &g_wth[(colB + row) * D_DIM + gk + c * 8]);
    }
    if (tid < 128) {                            // B rows 64..95
        int idx = tid + 256;
        int row = idx >> 2, c = idx & 3;
        cp16(st + A_OFF_B + row * 80 + c * 16, &g_wth[(colB + row) * D_DIM + gk + c * 8]);
    }
}

__device__ __forceinline__ void load_sim_stage(uint32_t st, int kc, int rowA, int colB, int tid) {
    int gk = kc * 32;
    #pragma unroll
    for (int i = 0; i < 2; i++) {
        int idx = tid + i * 256;
        int row = idx >> 2, c = idx & 3;
        cp16(st + row * 80 + c * 16,           &g_eh[(rowA + row) * D_DIM + gk + c * 8]);
        cp16(st + S_OFF_B + row * 80 + c * 16, &g_eh[(colB + row) * D_DIM + gk + c * 8]);
    }
}

__global__ void __launch_bounds__(256, 2) k_gemm(const int* __restrict__ labels) {
    extern __shared__ char smem[];
    uint32_t sb = smem_u32(smem);
    int tid = threadIdx.x, wid = tid >> 5, lane = tid & 31;
    int warpM = wid & 3, warpN = wid >> 2;          // 4M x 2N
    int bx = blockIdx.x;

    if (bx < ARC_BLKS) {
        // ------------------------- arc path -------------------------
        int rowA  = (bx & 15) * 128;
        int tileN = bx >> 4;
        int colB  = tileN * ABN;

        float acc[2][6][4];
        #pragma unroll
        for (int a = 0; a < 2; a++)
            #pragma unroll
            for (int b = 0; b < 6; b++)
                #pragma unroll
                for (int c = 0; c < 4; c++) acc[a][b][c] = 0.f;

        int lrow = lane & 15, lhalf = lane >> 4;
        uint32_t aoff[2], boff[3];
        #pragma unroll
        for (int mt = 0; mt < 2; mt++) aoff[mt] = (warpM * 32 + mt * 16 + lrow) * 80 + lhalf * 16;
        #pragma unroll
        for (int bg = 0; bg < 3; bg++) boff[bg] = A_OFF_B + (warpN * 48 + bg * 16 + lrow) * 80 + lhalf * 16;

        load_arc_stage(sb, 0, rowA, colB, tid); CP_COMMIT();
        load_arc_stage(sb + A_STG, 1, rowA, colB, tid); CP_COMMIT();

        #pragma unroll 1
        for (int kc = 0; kc < 16; kc++) {
            CP_WAIT1();
            __syncthreads();
            if (kc + 2 < 16)
                load_arc_stage(sb + ((kc + 2) % 3) * A_STG, kc + 2, rowA, colB, tid);
            CP_COMMIT();
            uint32_t st = sb + (kc % 3) * A_STG;
            #pragma unroll
            for (int ks = 0; ks < 2; ks++) {
                uint32_t ar[2][4], br[3][4];
                #pragma unroll
                for (int mt = 0; mt < 2; mt++) ldsm4(ar[mt], st + aoff[mt] + ks * 32);
                #pragma unroll
                for (int bg = 0; bg < 3; bg++) ldsm4(br[bg], st + boff[bg] + ks * 32);
                #pragma unroll
                for (int mt = 0; mt < 2; mt++)
                    #pragma unroll
                    for (int nt = 0; nt < 6; nt++) {
                        int bt = nt >> 1, sel = nt & 1;
                        mma_fp16(acc[mt][nt], ar[mt], br[bt][sel], br[bt][sel | 2]);
                    }
            }
        }

        // epilogue: accum -> smem (pitch 100 fp32), fused subcenter/margin/lse
        __syncthreads();
        float* se = (float*)smem;
        #pragma unroll
        for (int mt = 0; mt < 2; mt++) {
            int r = warpM * 32 + mt * 16 + (lane >> 2);
            #pragma unroll
            for (int nt = 0; nt < 6; nt++) {
                int c = warpN * 48 + nt * 8 + ((lane & 3) << 1);
                se[r * 100 + c]           = acc[mt][nt][0];
                se[r * 100 + c + 1]       = acc[mt][nt][1];
                se[(r + 8) * 100 + c]     = acc[mt][nt][2];
                se[(r + 8) * 100 + c + 1] = acc[mt][nt][3];
            }
        }
        __syncthreads();

        int r = tid >> 1, h = tid & 1;
        int gi = rowA + r;
        int lab = labels[gi];
        int cbase = tileN * 32 + h * 16;
        const float* row = se + r * 100 + h * 48;
        float M = -1e30f, S = 0.f;
        #pragma unroll
        for (int g = 0; g < 16; g++) {
            int c = cbase + g;
            if (c >= C_CLS) break;
            float cm = fmaxf(fmaxf(row[3*g], row[3*g+1]), row[3*g+2]);
            float logit;
            if (c == lab) {
                float cc = fminf(fmaxf(cm, -1.f + 1e-7f), 1.f - 1e-7f);
                float sn = sqrtf(fmaxf(1.f - cc * cc, 0.f));
                logit = ARC_S * (cc * COS_M - sn * SIN_M);
                g_lab[gi] = logit;
            } else {
                logit = ARC_S * cm;
            }
            lse_merge(M, S, logit, 1.f);
        }
        float pM = __shfl_xor_sync(0xffffffffu, M, 1);
        float pS = __shfl_xor_sync(0xffffffffu, S, 1);
        lse_merge(M, S, pM, pS);
        if (h == 0) {
            g_arc_m[gi * NTILES_G + tileN] = M;
            g_arc_s[gi * NTILES_G + tileN] = S;
        }
    } else {
        // ------------------------- sim path -------------------------
        int sidx = bx - ARC_BLKS;
        int rowA = (sidx & 15) * 128;
        int colB = (sidx >> 4) * 128;

        int* slab = (int*)(smem + 3 * S_STG);
        if (tid < 128) slab[tid] = labels[colB + tid];

        float acc[2][8][4];
        #pragma unroll
        for (int a = 0; a < 2; a++)
            #pragma unroll
            for (int b = 0; b < 8; b++)
                #pragma unroll
                for (int c = 0; c < 4; c++) acc[a][b][c] = 0.f;

        int lrow = lane & 15, lhalf = lane >> 4;
        uint32_t aoff[2], boff[4];
        #pragma unroll
        for (int mt = 0; mt < 2; mt++) aoff[mt] = (warpM * 32 + mt * 16 + lrow) * 80 + lhalf * 16;
        #pragma unroll
        for (int bg = 0; bg < 4; bg++) boff[bg] = S_OFF_B + (warpN * 64 + bg * 16 + lrow) * 80 + lhalf * 16;

        load_sim_stage(sb, 0, rowA, colB, tid); CP_COMMIT();
        load_sim_stage(sb + S_STG, 1, rowA, colB, tid); CP_COMMIT();

        #pragma unroll 1
        for (int kc = 0; kc < 16; kc++) {
            CP_WAIT1();
            __syncthreads();
            if (kc + 2 < 16)
                load_sim_stage(sb + ((kc + 2) % 3) * S_STG, kc + 2, rowA, colB, tid);
            CP_COMMIT();
            uint32_t st = sb + (kc % 3) * S_STG;
            #pragma unroll
            for (int ks = 0; ks < 2; ks++) {
                uint32_t ar[2][4], br[4][4];
                #pragma unroll
                for (int mt = 0; mt < 2; mt++) ldsm4(ar[mt], st + aoff[mt] + ks * 32);
                #pragma unroll
                for (int bg = 0; bg < 4; bg++) ldsm4(br[bg], st + boff[bg] + ks * 32);
                #pragma unroll
                for (int mt = 0; mt < 2; mt++)
                    #pragma unroll
                    for (int nt = 0; nt < 8; nt++) {
                        int bt = nt >> 1, sel = nt & 1;
                        mma_fp16(acc[mt][nt], ar[mt], br[bt][sel], br[bt][sel | 2]);
                    }
            }
        }

        // fused triplet epilogue
        #pragma unroll
        for (int mt = 0; mt < 2; mt++) {
            #pragma unroll
            for (int ro = 0; ro < 2; ro++) {
                int r = warpM * 32 + mt * 16 + (lane >> 2) + ro * 8;
                int gi = rowA + r;
                int myl = __ldg(&labels[gi]);
                float dap = -1.f, dan = 3.f;
                #pragma unroll
                for (int nt = 0; nt < 8; nt++) {
                    #pragma unroll
                    for (int j = 0; j < 2; j++) {
                        int cl = warpN * 64 + nt * 8 + ((lane & 3) << 1) + j;
                        int gj = colB + cl;
                        float sim  = acc[mt][nt][ro * 2 + j];
                        float dist = sqrtf(fmaxf(2.f - 2.f * sim, 0.f));
                        if (slab[cl] == myl) { if (gj != gi) dap = fmaxf(dap, dist); }
                        else                 { dan = fminf(dan, dist); }
                    }
                }
                #pragma unroll
                for (int off = 1; off < 4; off <<= 1) {
                    dap = fmaxf(dap, __shfl_xor_sync(0xffffffffu, dap, off));
                    dan = fminf(dan, __shfl_xor_sync(0xffffffffu, dan, off));
                }
                if ((lane & 3) == 0) {
                    atomicMax(&g_dap[gi], __float_as_int(dap));
                    atomicMin(&g_dan[gi], __float_as_int(dan));
                }
            }
        }
    }
}

// ---------------- arc reduce ----------------
__global__ void k_arc_reduce() {
    int row = blockIdx.x, tid = threadIdx.x;
    float M = -1e30f, S = 0.f;
    for (int t = tid; t < NTILES_G; t += 256)
        lse_merge(M, S, g_arc_m[row * NTILES_G + t], g_arc_s[row * NTILES_G + t]);
    __shared__ float sm[256], ss[256];
    sm[tid] = M; ss[tid] = S;
    __syncthreads();
    for (int st = 128; st > 0; st >>= 1) {
        if (tid < st) {
            float m1 = sm[tid], s1 = ss[tid];
            lse_merge(m1, s1, sm[tid + st], ss[tid + st]);
            sm[tid] = m1; ss[tid] = s1;
        }
        __syncthreads();
    }
    if (tid == 0) {
        float lse = sm[0] + logf(ss[0]);
        atomicAdd(&g_arc_sum, (double)(lse - g_lab[row]));
    }
}

// ---------------- center loss ----------------
__global__ void k_center(const int* __restrict__ labels, const float* __restrict__ centers) {
    int row = blockIdx.x, tid = threadIdx.x;
    int lab = labels[row];
    const float* c = centers + lab * D_DIM;
    const float* e = g_e + row * D_DIM;
    float s = 0.f;
    for (int d = tid; d < D_DIM; d += 256) { float diff = e[d] - c[d]; s += diff * diff; }
    __shared__ float red[256];
    red[tid] = s; __syncthreads();
    for (int st = 128; st > 0; st >>= 1) { if (tid < st) red[tid] += red[tid + st]; __syncthreads(); }
    if (tid == 0) atomicAdd(&g_center_sum, (double)red[0]);
}

// ---------------- finalize: triplet reduce + combine (one block) ----------------
__global__ void k_final(float* __restrict__ out) {
    int tid = threadIdx.x;
    float tl_loc = 0.f;
    int   nnz_loc = 0;
    for (int i = tid; i < N_SAMP; i += 256) {
        float dap = __int_as_float(g_dap[i]);
        float dan = __int_as_float(g_dan[i]);
        bool valid = (dap >= 0.f) && (dan < 2.5f);
        float tl = valid ? fmaxf(dap - dan + TRIP_M, 0.f) : 0.f;
        if (tl > 0.f) { tl_loc += tl; nnz_loc++; }
    }
    __shared__ float stl[256];
    __shared__ int   snz[256];
    stl[tid] = tl_loc; snz[tid] = nnz_loc;
    __syncthreads();
    for (int st = 128; st > 0; st >>= 1) {
        if (tid < st) { stl[tid] += stl[tid + st]; snz[tid] += snz[tid + st]; }
        __syncthreads();
    }
    if (tid == 0) {
        int nnz = snz[0] > 1 ? snz[0] : 1;
        double arc  = g_arc_sum / (double)N_SAMP;
        double trip = (double)stl[0] / (double)nnz;
        double cen  = g_center_sum / (double)N_SAMP;
        out[0] = (float)(arc + 0.5 * trip + 0.01 * cen);
    }
}

// ---------------- launch ----------------
#define WPREP_SMEM (512 * 33 * 4)

extern "C" void kernel_launch(void* const* d_in, const int* in_sizes, int n_in,
                              void* d_out, int out_size) {
    const float* emb     = (const float*)d_in[0];
    const int*   labels  = (const int*)  d_in[1];
    const float* W       = (const float*)d_in[2];
    const float* centers = (const float*)d_in[3];
    float* out = (float*)d_out;

    cudaFuncSetAttribute(k_gemm,  cudaFuncAttributeMaxDynamicSharedMemorySize, G_SMEM);
    cudaFuncSetAttribute(k_wprep, cudaFuncAttributeMaxDynamicSharedMemorySize, WPREP_SMEM);

    k_norm_emb<<<N_SAMP, 256>>>(emb);
    k_wprep<<<(CK + 31) / 32, 256, WPREP_SMEM>>>(W);
    k_gemm<<<ALL_BLKS, 256, G_SMEM>>>(labels);
    k_arc_reduce<<<N_SAMP, 256>>>();
    k_center<<<N_SAMP, 256>>>(labels, centers);
    k_final<<<1, 256>>>(out);
}

// round 11
// speedup vs baseline: 2.6801x; 1.0012x over previous
#include <cuda_runtime.h>
#include <cuda_fp16.h>
#include <math.h>
#include <stdint.h>

// ---------------- problem constants ----------------
#define N_SAMP 2048
#define D_DIM  512
#define C_CLS  10000
#define CK     30000
#define CK_PAD 30720
#define ARC_S  30.0f
#define COS_M  0.9210609940028851f   // cos(0.4)
#define SIN_M  0.3894183423086505f   // sin(0.4)
#define TRIP_M 0.3f

#define ABN      96                  // arc tile N (32 classes)
#define NTILES_G 313                 // ceil(30000/96) -> cols < 30048 (zero-padded)
#define ARC_BLKS (16 * NTILES_G)     // 5008
#define SIM_BLKS 256                 // 16 x 16
#define ALL_BLKS (ARC_BLKS + SIM_BLKS)

// ---------------- scratch ----------------
__device__ __align__(128) float  g_e[N_SAMP * D_DIM];   // exact normalized (center loss)
__device__ __align__(128) __half g_eh[N_SAMP * D_DIM];  // fp16 normalized (both GEMMs)
__device__ __align__(128) __half g_wth[CK_PAD * D_DIM]; // fp16 transposed normalized W;
                                                        // rows >= 30000 never written (stay 0)
__device__ float  g_arc_m[N_SAMP * NTILES_G];
__device__ float  g_arc_s[N_SAMP * NTILES_G];
__device__ float  g_lab[N_SAMP];
__device__ int    g_dap[N_SAMP];
__device__ int    g_dan[N_SAMP];
__device__ double g_arc_sum, g_center_sum;

// ---------------- PTX helpers (sm_80-era, plain-target safe) ----------------
__device__ __forceinline__ uint32_t smem_u32(const void* p) {
    uint32_t a;
    asm("{ .reg .u64 t; cvta.to.shared.u64 t, %1; cvt.u32.u64 %0, t; }" : "=r"(a) : "l"(p));
    return a;
}
__device__ __forceinline__ void cp16(uint32_t dst, const void* src) {
    asm volatile("cp.async.cg.shared.global [%0], [%1], 16;" :: "r"(dst), "l"(src) : "memory");
}
#define CP_COMMIT() asm volatile("cp.async.commit_group;" ::: "memory")
#define CP_WAIT1()  asm volatile("cp.async.wait_group 1;" ::: "memory")

__device__ __forceinline__ void ldsm4(uint32_t* r, uint32_t addr) {
    asm volatile("ldmatrix.sync.aligned.m8n8.x4.shared.b16 {%0,%1,%2,%3}, [%4];"
        : "=r"(r[0]), "=r"(r[1]), "=r"(r[2]), "=r"(r[3]) : "r"(addr));
}
__device__ __forceinline__ void mma_fp16(float* d, const uint32_t* a, uint32_t b0, uint32_t b1) {
    asm volatile("mma.sync.aligned.m16n8k16.row.col.f32.f16.f16.f32 "
        "{%0,%1,%2,%3}, {%4,%5,%6,%7}, {%8,%9}, {%0,%1,%2,%3};"
        : "+f"(d[0]), "+f"(d[1]), "+f"(d[2]), "+f"(d[3])
        : "r"(a[0]), "r"(a[1]), "r"(a[2]), "r"(a[3]), "r"(b0), "r"(b1));
}
__device__ __forceinline__ void lse_merge(float& M, float& S, float m2, float s2) {
    if (m2 > M) { S = S * expf(M - m2) + s2; M = m2; }
    else        { S += s2 * expf(m2 - M); }
}

// ---------------- norm_emb (+ per-row init, + global sums zero) ----------------
__global__ void k_norm_emb(const float* __restrict__ emb) {
    int row = blockIdx.x, tid = threadIdx.x;
    if (tid == 0) {
        g_dap[row] = __float_as_int(-1.0f);
        g_dan[row] = __float_as_int(3.0f);
        if (row == 0) { g_arc_sum = 0.0; g_center_sum = 0.0; }
    }
    const float* src = emb + row * D_DIM;
    float s = 0.f;
    for (int d = tid; d < D_DIM; d += 256) { float v = src[d]; s += v * v; }
    __shared__ float red[256];
    red[tid] = s; __syncthreads();
    for (int st = 128; st > 0; st >>= 1) { if (tid < st) red[tid] += red[tid + st]; __syncthreads(); }
    float inv = 1.f / fmaxf(sqrtf(red[0]), 1e-12f);
    for (int d = tid; d < D_DIM; d += 256) {
        float v = src[d] * inv;
        g_e[row * D_DIM + d]  = v;
        g_eh[row * D_DIM + d] = __float2half_rn(v);
    }
}

// ---------------- fused W prep: norm + transpose + fp16, W read ONCE ----------
// block = 256 thr (8 warps), handles 32 columns x all 512 k.
// dyn smem: values [512][33] fp32 = 67584 B
__global__ void k_wprep(const float* __restrict__ W) {
    extern __shared__ char smem[];
    float* sv = (float*)smem;                 // [k][j] pitch 33
    __shared__ float part[8][32];
    __shared__ float sinv[32];
    int tid = threadIdx.x, w = tid >> 5, l = tid & 31;
    int j0 = blockIdx.x * 32;
    int j  = j0 + l;
    bool ok = j < CK;

    float s = 0.f;
    int kbase = w * 64;
    #pragma unroll 8
    for (int kk = 0; kk < 64; kk++) {
        int k = kbase + kk;
        float v = ok ? W[k * CK + j] : 0.f;
        sv[k * 33 + l] = v;
        s += v * v;
    }
    part[w][l] = s;
    __syncthreads();
    if (w == 0) {
        float t = 0.f;
        #pragma unroll
        for (int r = 0; r < 8; r++) t += part[r][l];
        sinv[l] = 1.f / fmaxf(sqrtf(t), 1e-12f);
    }
    __syncthreads();

    // write transposed fp16: warp w -> j-rows w*4 .. w*4+3
    #pragma unroll
    for (int rr = 0; rr < 4; rr++) {
        int jl = w * 4 + rr, jg = j0 + jl;
        if (jg >= CK) continue;
        float inv = sinv[jl];
        #pragma unroll
        for (int it = 0; it < 8; it++) {
            int k = it * 64 + l * 2;
            float v0 = sv[k * 33 + jl] * inv;
            float v1 = sv[(k + 1) * 33 + jl] * inv;
            *(__half2*)&g_wth[jg * D_DIM + k] = __floats2half2_rn(v0, v1);
        }
    }
}

// ============================================================================
// fused GEMM kernel: blocks [0, 5008) = arc 128x96, blocks [5008, 5264) = sim 128x128
// Both single-pass fp16 m16n8k16, 3-stage cp.async, 80B-pitch SMEM rows.
// arc stage 17920 (A 10240 | B 7680); sim stage 20480 (A 10240 | B 10240)
// SMEM = 3*20480 + 512 = 61952 -> 2 CTA/SM
// ============================================================================
#define A_OFF_B  10240
#define A_STG    17920
#define S_OFF_B  10240
#define S_STG    20480
#define G_SMEM   (3 * S_STG + 512)

__device__ __forceinline__ void load_arc_stage(uint32_t st, int kc, int rowA, int colB, int tid) {
    int gk = kc * 32;
    #pragma unroll
    for (int i = 0; i < 2; i++) {               // A: 128 rows x 4 segs of 16B
        int idx = tid + i * 256;
        int row = idx >> 2, c = idx & 3;
        cp16(st + row * 80 + c * 16, &g_eh[(rowA + row) * D_DIM + gk + c * 8]);
    }
    {                                           // B rows 0..63
        int row = tid >> 2, c = tid & 3;
        cp16(st + A_OFF_B + row * 80 + c * 16, &g_wth[(colB + row) * D_DIM + gk + c * 8]);
    }
    if (tid < 128) {                            // B rows 64..95
        int idx = tid + 256;
        int row = idx >> 2, c = idx & 3;
        cp16(st + A_OFF_B + row * 80 + c * 16, &g_wth[(colB + row) * D_DIM + gk + c * 8]);
    }
}

__device__ __forceinline__ void load_sim_stage(uint32_t st, int kc, int rowA, int colB, int tid) {
    int gk = kc * 32;
    #pragma unroll
    for (int i = 0; i < 2; i++) {
        int idx = tid + i * 256;
        int row = idx >> 2, c = idx & 3;
        cp16(st + row * 80 + c * 16,           &g_eh[(rowA + row) * D_DIM + gk + c * 8]);
        cp16(st + S_OFF_B + row * 80 + c * 16, &g_eh[(colB + row) * D_DIM + gk + c * 8]);
    }
}

__global__ void __launch_bounds__(256, 2) k_gemm(const int* __restrict__ labels) {
    extern __shared__ char smem[];
    uint32_t sb = smem_u32(smem);
    int tid = threadIdx.x, wid = tid >> 5, lane = tid & 31;
    int warpM = wid & 3, warpN = wid >> 2;          // 4M x 2N
    int bx = blockIdx.x;

    if (bx < ARC_BLKS) {
        // ------------------------- arc path -------------------------
        int rowA  = (bx & 15) * 128;
        int tileN = bx >> 4;
        int colB  = tileN * ABN;

        float acc[2][6][4];
        #pragma unroll
        for (int a = 0; a < 2; a++)
            #pragma unroll
            for (int b = 0; b < 6; b++)
                #pragma unroll
                for (int c = 0; c < 4; c++) acc[a][b][c] = 0.f;

        int lrow = lane & 15, lhalf = lane >> 4;
        uint32_t aoff[2], boff[3];
        #pragma unroll
        for (int mt = 0; mt < 2; mt++) aoff[mt] = (warpM * 32 + mt * 16 + lrow) * 80 + lhalf * 16;
        #pragma unroll
        for (int bg = 0; bg < 3; bg++) boff[bg] = A_OFF_B + (warpN * 48 + bg * 16 + lrow) * 80 + lhalf * 16;

        load_arc_stage(sb, 0, rowA, colB, tid); CP_COMMIT();
        load_arc_stage(sb + A_STG, 1, rowA, colB, tid); CP_COMMIT();

        #pragma unroll 1
        for (int kc = 0; kc < 16; kc++) {
            CP_WAIT1();
            __syncthreads();
            if (kc + 2 < 16)
                load_arc_stage(sb + ((kc + 2) % 3) * A_STG, kc + 2, rowA, colB, tid);
            CP_COMMIT();
            uint32_t st = sb + (kc % 3) * A_STG;
            #pragma unroll
            for (int ks = 0; ks < 2; ks++) {
                uint32_t ar[2][4], br[3][4];
                #pragma unroll
                for (int mt = 0; mt < 2; mt++) ldsm4(ar[mt], st + aoff[mt] + ks * 32);
                #pragma unroll
                for (int bg = 0; bg < 3; bg++) ldsm4(br[bg], st + boff[bg] + ks * 32);
                #pragma unroll
                for (int mt = 0; mt < 2; mt++)
                    #pragma unroll
                    for (int nt = 0; nt < 6; nt++) {
                        int bt = nt >> 1, sel = nt & 1;
                        mma_fp16(acc[mt][nt], ar[mt], br[bt][sel], br[bt][sel | 2]);
                    }
            }
        }

        // epilogue: accum -> smem (pitch 100 fp32), fused subcenter/margin/lse
        __syncthreads();
        float* se = (float*)smem;
        #pragma unroll
        for (int mt = 0; mt < 2; mt++) {
            int r = warpM * 32 + mt * 16 + (lane >> 2);
            #pragma unroll
            for (int nt = 0; nt < 6; nt++) {
                int c = warpN * 48 + nt * 8 + ((lane & 3) << 1);
                se[r * 100 + c]           = acc[mt][nt][0];
                se[r * 100 + c + 1]       = acc[mt][nt][1];
                se[(r + 8) * 100 + c]     = acc[mt][nt][2];
                se[(r + 8) * 100 + c + 1] = acc[mt][nt][3];
            }
        }
        __syncthreads();

        int r = tid >> 1, h = tid & 1;
        int gi = rowA + r;
        int lab = labels[gi];
        int cbase = tileN * 32 + h * 16;
        const float* row = se + r * 100 + h * 48;
        float M = -1e30f, S = 0.f;
        #pragma unroll
        for (int g = 0; g < 16; g++) {
            int c = cbase + g;
            if (c >= C_CLS) break;
            float cm = fmaxf(fmaxf(row[3*g], row[3*g+1]), row[3*g+2]);
            float logit;
            if (c == lab) {
                float cc = fminf(fmaxf(cm, -1.f + 1e-7f), 1.f - 1e-7f);
                float sn = sqrtf(fmaxf(1.f - cc * cc, 0.f));
                logit = ARC_S * (cc * COS_M - sn * SIN_M);
                g_lab[gi] = logit;
            } else {
                logit = ARC_S * cm;
            }
            lse_merge(M, S, logit, 1.f);
        }
        float pM = __shfl_xor_sync(0xffffffffu, M, 1);
        float pS = __shfl_xor_sync(0xffffffffu, S, 1);
        lse_merge(M, S, pM, pS);
        if (h == 0) {
            g_arc_m[gi * NTILES_G + tileN] = M;
            g_arc_s[gi * NTILES_G + tileN] = S;
        }
    } else {
        // ------------------------- sim path -------------------------
        int sidx = bx - ARC_BLKS;
        int rowA = (sidx & 15) * 128;
        int colB = (sidx >> 4) * 128;

        int* slab = (int*)(smem + 3 * S_STG);
        if (tid < 128) slab[tid] = labels[colB + tid];

        float acc[2][8][4];
        #pragma unroll
        for (int a = 0; a < 2; a++)
            #pragma unroll
            for (int b = 0; b < 8; b++)
                #pragma unroll
                for (int c = 0; c < 4; c++) acc[a][b][c] = 0.f;

        int lrow = lane & 15, lhalf = lane >> 4;
        uint32_t aoff[2], boff[4];
        #pragma unroll
        for (int mt = 0; mt < 2; mt++) aoff[mt] = (warpM * 32 + mt * 16 + lrow) * 80 + lhalf * 16;
        #pragma unroll
        for (int bg = 0; bg < 4; bg++) boff[bg] = S_OFF_B + (warpN * 64 + bg * 16 + lrow) * 80 + lhalf * 16;

        load_sim_stage(sb, 0, rowA, colB, tid); CP_COMMIT();
        load_sim_stage(sb + S_STG, 1, rowA, colB, tid); CP_COMMIT();

        #pragma unroll 1
        for (int kc = 0; kc < 16; kc++) {
            CP_WAIT1();
            __syncthreads();
            if (kc + 2 < 16)
                load_sim_stage(sb + ((kc + 2) % 3) * S_STG, kc + 2, rowA, colB, tid);
            CP_COMMIT();
            uint32_t st = sb + (kc % 3) * S_STG;
            #pragma unroll
            for (int ks = 0; ks < 2; ks++) {
                uint32_t ar[2][4], br[4][4];
                #pragma unroll
                for (int mt = 0; mt < 2; mt++) ldsm4(ar[mt], st + aoff[mt] + ks * 32);
                #pragma unroll
                for (int bg = 0; bg < 4; bg++) ldsm4(br[bg], st + boff[bg] + ks * 32);
                #pragma unroll
                for (int mt = 0; mt < 2; mt++)
                    #pragma unroll
                    for (int nt = 0; nt < 8; nt++) {
                        int bt = nt >> 1, sel = nt & 1;
                        mma_fp16(acc[mt][nt], ar[mt], br[bt][sel], br[bt][sel | 2]);
                    }
            }
        }

        // fused triplet epilogue
        #pragma unroll
        for (int mt = 0; mt < 2; mt++) {
            #pragma unroll
            for (int ro = 0; ro < 2; ro++) {
                int r = warpM * 32 + mt * 16 + (lane >> 2) + ro * 8;
                int gi = rowA + r;
                int myl = __ldg(&labels[gi]);
                float dap = -1.f, dan = 3.f;
                #pragma unroll
                for (int nt = 0; nt < 8; nt++) {
                    #pragma unroll
                    for (int j = 0; j < 2; j++) {
                        int cl = warpN * 64 + nt * 8 + ((lane & 3) << 1) + j;
                        int gj = colB + cl;
                        float sim  = acc[mt][nt][ro * 2 + j];
                        float dist = sqrtf(fmaxf(2.f - 2.f * sim, 0.f));
                        if (slab[cl] == myl) { if (gj != gi) dap = fmaxf(dap, dist); }
                        else                 { dan = fminf(dan, dist); }
                    }
                }
                #pragma unroll
                for (int off = 1; off < 4; off <<= 1) {
                    dap = fmaxf(dap, __shfl_xor_sync(0xffffffffu, dap, off));
                    dan = fminf(dan, __shfl_xor_sync(0xffffffffu, dan, off));
                }
                if ((lane & 3) == 0) {
                    atomicMax(&g_dap[gi], __float_as_int(dap));
                    atomicMin(&g_dan[gi], __float_as_int(dan));
                }
            }
        }
    }
}

// ---------------- arc reduce ----------------
__global__ void k_arc_reduce() {
    int row = blockIdx.x, tid = threadIdx.x;
    float M = -1e30f, S = 0.f;
    for (int t = tid; t < NTILES_G; t += 256)
        lse_merge(M, S, g_arc_m[row * NTILES_G + t], g_arc_s[row * NTILES_G + t]);
    __shared__ float sm[256], ss[256];
    sm[tid] = M; ss[tid] = S;
    __syncthreads();
    for (int st = 128; st > 0; st >>= 1) {
        if (tid < st) {
            float m1 = sm[tid], s1 = ss[tid];
            lse_merge(m1, s1, sm[tid + st], ss[tid + st]);
            sm[tid] = m1; ss[tid] = s1;
        }
        __syncthreads();
    }
    if (tid == 0) {
        float lse = sm[0] + logf(ss[0]);
        atomicAdd(&g_arc_sum, (double)(lse - g_lab[row]));
    }
}

// ---------------- center loss ----------------
__global__ void k_center(const int* __restrict__ labels, const float* __restrict__ centers) {
    int row = blockIdx.x, tid = threadIdx.x;
    int lab = labels[row];
    const float* c = centers + lab * D_DIM;
    const float* e = g_e + row * D_DIM;
    float s = 0.f;
    for (int d = tid; d < D_DIM; d += 256) { float diff = e[d] - c[d]; s += diff * diff; }
    __shared__ float red[256];
    red[tid] = s; __syncthreads();
    for (int st = 128; st > 0; st >>= 1) { if (tid < st) red[tid] += red[tid + st]; __syncthreads(); }
    if (tid == 0) atomicAdd(&g_center_sum, (double)red[0]);
}

// ---------------- finalize: triplet reduce + combine (one block) ----------------
__global__ void k_final(float* __restrict__ out) {
    int tid = threadIdx.x;
    float tl_loc = 0.f;
    int   nnz_loc = 0;
    for (int i = tid; i < N_SAMP; i += 256) {
        float dap = __int_as_float(g_dap[i]);
        float dan = __int_as_float(g_dan[i]);
        bool valid = (dap >= 0.f) && (dan < 2.5f);
        float tl = valid ? fmaxf(dap - dan + TRIP_M, 0.f) : 0.f;
        if (tl > 0.f) { tl_loc += tl; nnz_loc++; }
    }
    __shared__ float stl[256];
    __shared__ int   snz[256];
    stl[tid] = tl_loc; snz[tid] = nnz_loc;
    __syncthreads();
    for (int st = 128; st > 0; st >>= 1) {
        if (tid < st) { stl[tid] += stl[tid + st]; snz[tid] += snz[tid + st]; }
        __syncthreads();
    }
    if (tid == 0) {
        int nnz = snz[0] > 1 ? snz[0] : 1;
        double arc  = g_arc_sum / (double)N_SAMP;
        double trip = (double)stl[0] / (double)nnz;
        double cen  = g_center_sum / (double)N_SAMP;
        out[0] = (float)(arc + 0.5 * trip + 0.01 * cen);
    }
}

// ---------------- launch ----------------
#define WPREP_SMEM (512 * 33 * 4)

extern "C" void kernel_launch(void* const* d_in, const int* in_sizes, int n_in,
                              void* d_out, int out_size) {
    const float* emb     = (const float*)d_in[0];
    const int*   labels  = (const int*)  d_in[1];
    const float* W       = (const float*)d_in[2];
    const float* centers = (const float*)d_in[3];
    float* out = (float*)d_out;

    cudaFuncSetAttribute(k_gemm,  cudaFuncAttributeMaxDynamicSharedMemorySize, G_SMEM);
    cudaFuncSetAttribute(k_wprep, cudaFuncAttributeMaxDynamicSharedMemorySize, WPREP_SMEM);

    k_norm_emb<<<N_SAMP, 256>>>(emb);
    k_wprep<<<(CK + 31) / 32, 256, WPREP_SMEM>>>(W);
    k_gemm<<<ALL_BLKS, 256, G_SMEM>>>(labels);
    k_arc_reduce<<<N_SAMP, 256>>>();
    k_center<<<N_SAMP, 256>>>(labels, centers);
    k_final<<<1, 256>>>(out);
}